// round 1
// baseline (speedup 1.0000x reference)
#include <cuda_runtime.h>
#include <math.h>

// ---------------- problem constants ----------------
#define NB     1024      // batch
#define NV     6890      // vertices
#define NJ     24        // joints
#define NBETA  10
#define NPOSE  207       // 23*9
// feature rows per channel c: t = 0..206 pose, 207..216 beta, 217 template, 218 ones(S0), 219..223 pad
#define TROWS  224
#define M2     672       // 3 * TROWS
#define M2PAD  704       // 11 * 64
#define N2     576       // jk = j*24+k
#define KPAD   6912      // vertices padded to 16*432
#define KSPLIT 8
#define KCHUNK 864       // KPAD / KSPLIT, = 54*16
#define GDIM   224       // padded feature count (218 valid)

__constant__ int c_parents[24] = {-1,0,0,0,1,2,3,4,5,6,7,8,9,9,9,12,13,14,16,17,18,19,20,21};

// ---------------- scratch (device globals; no allocation in kernel_launch) ----------------
__device__ float d_Pt[M2PAD * KPAD];          // 19.5 MB  P transposed+gathered
__device__ float d_JW[KPAD * N2];             // 15.9 MB  Jr[v,j]*w[v,k]
__device__ float d_Cpart[KSPLIT * M2PAD * N2];// 12.9 MB  split-K partials
__device__ float d_C2[M2 * N2];               // 1.55 MB  projected basis
__device__ float d_Jb[3 * 11 * NJ];           // rest-joint basis
__device__ float d_g[NB * GDIM];              // per-batch features (zero-padded tail)
__device__ float d_Rs[NB * NJ * 9];           // rotations
__device__ float d_Qv[NB * 1728];             // Qv[b][c][jk]

// ---------------- kernel 1: gather/transpose P into Pt[m][v] ----------------
__global__ void k_prep(const float* __restrict__ posedirs,
                       const float* __restrict__ shapedirs,
                       const float* __restrict__ vtempl,
                       float* __restrict__ Pt)
{
    int v = blockIdx.x * 256 + threadIdx.x;   // 0..6911
    int m = blockIdx.y;                       // 0..703
    float val = 0.f;
    if (m < M2 && v < NV) {
        int c = m / TROWS;
        int t = m - c * TROWS;
        if (t < NPOSE)            val = posedirs[t * (NV*3) + v*3 + c];
        else if (t < NPOSE+NBETA) val = shapedirs[(t-NPOSE) * (NV*3) + v*3 + c];
        else if (t == 217)        val = vtempl[v*3 + c];
        else if (t == 218)        val = (c == 0) ? 1.f : 0.f;
        // t in 219..223 -> 0
    }
    Pt[(size_t)m * KPAD + v] = val;
}

// ---------------- kernel 2: JW[v][jk] = Jr[v,j]*w[v,k] ----------------
__global__ void k_jw(const float* __restrict__ Jr,
                     const float* __restrict__ w,
                     float* __restrict__ JW)
{
    int idx = blockIdx.x * 256 + threadIdx.x;   // < KPAD*N2
    int v  = idx / N2;
    int jk = idx - v * N2;
    float val = 0.f;
    if (v < NV) {
        int j = jk / 24, k = jk - j * 24;
        val = Jr[v*24 + j] * w[v*24 + k];
    }
    JW[idx] = val;
}

// ---------------- kernel 3: big GEMM  Cpart[s] += Pt[64 rows] @ JW ----------------
// M=704, N=576, K=6912 (split 8). 64x64 block tile, 128 threads, 8x4 per thread.
__global__ __launch_bounds__(128) void k_gemm2(const float* __restrict__ Pt,
                                               const float* __restrict__ JW,
                                               float* __restrict__ Cpart)
{
    __shared__ float As[16][68];
    __shared__ float Bs[16][64];
    const int tid = threadIdx.x;
    const int n0 = blockIdx.x * 64;
    const int m0 = blockIdx.y * 64;
    const int k0 = blockIdx.z * KCHUNK;

    const int tm = tid & 7;    // 8 row-groups
    const int tn = tid >> 3;   // 16 col-groups
    const int lk = tid & 15;   // A loader: kk
    const int lm = tid >> 4;   // A loader: mm base
    const int ln = tid & 63;   // B loader: nn
    const int lkb = tid >> 6;  // B loader: kk base

    float acc[8][4];
#pragma unroll
    for (int i = 0; i < 8; i++)
#pragma unroll
        for (int j = 0; j < 4; j++) acc[i][j] = 0.f;

    for (int kt = 0; kt < KCHUNK/16; ++kt) {
        const int kb = k0 + kt * 16;
#pragma unroll
        for (int q = 0; q < 8; q++)
            As[lk][lm + q*8] = Pt[(size_t)(m0 + lm + q*8) * KPAD + kb + lk];
#pragma unroll
        for (int q = 0; q < 8; q++)
            Bs[lkb + q*2][ln] = JW[(size_t)(kb + lkb + q*2) * N2 + n0 + ln];
        __syncthreads();
#pragma unroll
        for (int kk = 0; kk < 16; kk++) {
            float a[8], b[4];
            *(float4*)&a[0] = *(const float4*)&As[kk][tm*8];
            *(float4*)&a[4] = *(const float4*)&As[kk][tm*8+4];
            *(float4*)&b[0] = *(const float4*)&Bs[kk][tn*4];
#pragma unroll
            for (int i = 0; i < 8; i++)
#pragma unroll
                for (int j = 0; j < 4; j++)
                    acc[i][j] = fmaf(a[i], b[j], acc[i][j]);
        }
        __syncthreads();
    }
    float* cp = Cpart + (size_t)blockIdx.z * (M2PAD * N2);
#pragma unroll
    for (int i = 0; i < 8; i++) {
        int m = m0 + tm*8 + i;
        *(float4*)&cp[(size_t)m * N2 + n0 + tn*4] =
            make_float4(acc[i][0], acc[i][1], acc[i][2], acc[i][3]);
    }
}

// ---------------- kernel 4: reduce split-K partials into C2 ----------------
__global__ void k_reduce(const float* __restrict__ Cpart, float* __restrict__ C2)
{
    int idx = blockIdx.x * 256 + threadIdx.x;   // < M2*N2
    if (idx >= M2 * N2) return;
    float s = 0.f;
#pragma unroll
    for (int p = 0; p < KSPLIT; p++)
        s += Cpart[(size_t)p * (M2PAD*N2) + idx];
    C2[idx] = s;
}

// ---------------- kernel 5: rest-joint basis Jb[c][i][j] = sum_k C2 rows ----------------
__global__ void k_jb(const float* __restrict__ C2, float* __restrict__ Jb)
{
    int idx = blockIdx.x * 256 + threadIdx.x;
    if (idx >= 3*11*NJ) return;
    int c = idx / (11*NJ);
    int r = idx - c * (11*NJ);
    int i = r / NJ;           // 0..9 beta, 10 = template
    int j = r - i * NJ;
    const float* row = C2 + (size_t)(c*TROWS + 207 + i) * N2 + j*24;
    float s = 0.f;
#pragma unroll
    for (int k = 0; k < 24; k++) s += row[k];
    Jb[idx] = s;
}

// ---------------- kernel 6: Rodrigues + features g ----------------
__global__ void k_feat(const float* __restrict__ beta,
                       const float* __restrict__ theta,
                       float* __restrict__ g, float* __restrict__ Rs)
{
    int b = blockIdx.x;
    int lane = threadIdx.x;
    if (lane < 24) {
        int k = lane;
        float t0 = theta[b*72 + k*3 + 0];
        float t1 = theta[b*72 + k*3 + 1];
        float t2 = theta[b*72 + k*3 + 2];
        float a0 = t0 + 1e-8f, a1 = t1 + 1e-8f, a2 = t2 + 1e-8f;
        float angle = sqrtf(a0*a0 + a1*a1 + a2*a2);
        float inv = 1.f / angle;
        float n0 = t0*inv, n1 = t1*inv, n2 = t2*inv;
        float half = 0.5f * angle;
        float w = cosf(half), s = sinf(half);
        float x = s*n0, y = s*n1, z = s*n2;
        float qn = rsqrtf(w*w + x*x + y*y + z*z);
        w *= qn; x *= qn; y *= qn; z *= qn;
        float rot[9];
        rot[0] = w*w + x*x - y*y - z*z;
        rot[1] = 2.f*(x*y - w*z);
        rot[2] = 2.f*(x*z + w*y);
        rot[3] = 2.f*(x*y + w*z);
        rot[4] = w*w - x*x + y*y - z*z;
        rot[5] = 2.f*(y*z - w*x);
        rot[6] = 2.f*(x*z - w*y);
        rot[7] = 2.f*(y*z + w*x);
        rot[8] = w*w - x*x - y*y + z*z;
        float* rs = Rs + (size_t)(b*24 + k) * 9;
#pragma unroll
        for (int e = 0; e < 9; e++) rs[e] = rot[e];
        if (k > 0) {
            float* gp = g + (size_t)b * GDIM + (k-1)*9;
#pragma unroll
            for (int e = 0; e < 9; e++)
                gp[e] = rot[e] - ((e == 0 || e == 4 || e == 8) ? 1.f : 0.f);
        }
    }
    if (lane < 10)               g[(size_t)b*GDIM + 207 + lane] = beta[b*10 + lane];
    else if (lane == 10)         g[(size_t)b*GDIM + 217] = 1.f;
    else if (lane < 17)          g[(size_t)b*GDIM + 207 + lane] = 0.f; // pad 218..223
}

// ---------------- kernel 7: small GEMM  Qv[b][n] = g[b] @ C2 ----------------
// M=1024, N=1728 (c folded), K=224. 64x64 tile, 128 threads, 8x4.
__global__ __launch_bounds__(128) void k_gemm3(const float* __restrict__ g,
                                               const float* __restrict__ C2,
                                               float* __restrict__ Qv)
{
    __shared__ float As[16][68];
    __shared__ float Bs[16][64];
    const int tid = threadIdx.x;
    const int bx = blockIdx.x;          // 0..26
    const int n0g = bx * 64;
    const int c = bx / 9;
    const int nloc0 = (bx - c*9) * 64;
    const int m0 = blockIdx.y * 64;

    const int tm = tid & 7;
    const int tn = tid >> 3;
    const int lk = tid & 15;
    const int lm = tid >> 4;
    const int ln = tid & 63;
    const int lkb = tid >> 6;

    float acc[8][4];
#pragma unroll
    for (int i = 0; i < 8; i++)
#pragma unroll
        for (int j = 0; j < 4; j++) acc[i][j] = 0.f;

    for (int kt = 0; kt < GDIM/16; ++kt) {
        const int kb = kt * 16;
#pragma unroll
        for (int q = 0; q < 8; q++)
            As[lk][lm + q*8] = g[(size_t)(m0 + lm + q*8) * GDIM + kb + lk];
#pragma unroll
        for (int q = 0; q < 8; q++)
            Bs[lkb + q*2][ln] = C2[(size_t)(c*TROWS + kb + lkb + q*2) * N2 + nloc0 + ln];
        __syncthreads();
#pragma unroll
        for (int kk = 0; kk < 16; kk++) {
            float a[8], b[4];
            *(float4*)&a[0] = *(const float4*)&As[kk][tm*8];
            *(float4*)&a[4] = *(const float4*)&As[kk][tm*8+4];
            *(float4*)&b[0] = *(const float4*)&Bs[kk][tn*4];
#pragma unroll
            for (int i = 0; i < 8; i++)
#pragma unroll
                for (int j = 0; j < 4; j++)
                    acc[i][j] = fmaf(a[i], b[j], acc[i][j]);
        }
        __syncthreads();
    }
#pragma unroll
    for (int i = 0; i < 8; i++) {
        int m = m0 + tm*8 + i;
        *(float4*)&Qv[(size_t)m * 1728 + n0g + tn*4] =
            make_float4(acc[i][0], acc[i][1], acc[i][2], acc[i][3]);
    }
}

// ---------------- kernel 8: kinematic chain + final combine ----------------
__global__ __launch_bounds__(128) void k_final(const float* __restrict__ beta,
                                               const float* __restrict__ Rs,
                                               const float* __restrict__ Jb,
                                               const float* __restrict__ C2,
                                               const float* __restrict__ Qv,
                                               float* __restrict__ out)
{
    __shared__ float sR[216];      // 24 rotations
    __shared__ float sJ[72];       // rest joints [j][c]
    __shared__ float sG[288];      // 24 global transforms, 3x4 row-major
    __shared__ float sAt[72];      // translation column of A
    __shared__ float sBeta[10];
    const int b = blockIdx.x;
    const int tid = threadIdx.x;

    for (int i = tid; i < 216; i += 128) sR[i] = Rs[(size_t)b*216 + i];
    if (tid < 10) sBeta[tid] = beta[b*10 + tid];
    __syncthreads();

    if (tid < 72) {
        int j = tid / 3, c = tid - j*3;
        float v = Jb[(c*11 + 10)*NJ + j];
#pragma unroll
        for (int i = 0; i < 10; i++) v = fmaf(sBeta[i], Jb[(c*11 + i)*NJ + j], v);
        sJ[j*3 + c] = v;
    }
    __syncthreads();

    if (tid < 12) {
        int r = tid >> 2, cc = tid & 3;
        sG[tid] = (cc < 3) ? sR[r*3 + cc] : sJ[r];
        __syncwarp(0x0fff);
        for (int i = 1; i < 24; i++) {
            int p = c_parents[i];
            float v;
            if (cc < 3) {
                v = sG[p*12 + r*4 + 0] * sR[i*9 + 0 + cc]
                  + sG[p*12 + r*4 + 1] * sR[i*9 + 3 + cc]
                  + sG[p*12 + r*4 + 2] * sR[i*9 + 6 + cc];
            } else {
                float tx = sJ[i*3+0] - sJ[p*3+0];
                float ty = sJ[i*3+1] - sJ[p*3+1];
                float tz = sJ[i*3+2] - sJ[p*3+2];
                v = sG[p*12 + r*4 + 0] * tx
                  + sG[p*12 + r*4 + 1] * ty
                  + sG[p*12 + r*4 + 2] * tz
                  + sG[p*12 + r*4 + 3];
            }
            sG[i*12 + r*4 + cc] = v;
            __syncwarp(0x0fff);
        }
    }
    __syncthreads();

    if (tid < 72) {
        int k = tid / 3, c = tid - k*3;
        sAt[k*3 + c] = sG[k*12 + c*4 + 3]
                     - (sG[k*12 + c*4 + 0] * sJ[k*3 + 0]
                      + sG[k*12 + c*4 + 1] * sJ[k*3 + 1]
                      + sG[k*12 + c*4 + 2] * sJ[k*3 + 2]);
    }
    __syncthreads();

    if (tid < 72) {
        int j = tid / 3, c = tid - j*3;
        const float* qb = Qv + (size_t)b * 1728;
        const float* s0 = C2 + 218 * N2;   // (c=0, t=218) row = S0[jk]
        float acc = 0.f;
#pragma unroll
        for (int k = 0; k < 24; k++) {
            int jk = j*24 + k;
            acc = fmaf(sG[k*12 + c*4 + 0], qb[jk],        acc);
            acc = fmaf(sG[k*12 + c*4 + 1], qb[576 + jk],  acc);
            acc = fmaf(sG[k*12 + c*4 + 2], qb[1152 + jk], acc);
            acc = fmaf(sAt[k*3 + c],       s0[jk],        acc);
        }
        out[b*72 + j*3 + c] = acc;
    }
}

// ---------------- launcher ----------------
extern "C" void kernel_launch(void* const* d_in, const int* in_sizes, int n_in,
                              void* d_out, int out_size)
{
    const float* beta     = (const float*)d_in[0];   // [1024,10]
    const float* theta    = (const float*)d_in[1];   // [1024,72]
    const float* vtempl   = (const float*)d_in[2];   // [6890,3]
    const float* shapedirs= (const float*)d_in[3];   // [10,20670]
    const float* posedirs = (const float*)d_in[4];   // [207,20670]
    const float* Jr       = (const float*)d_in[5];   // [6890,24]
    const float* wts      = (const float*)d_in[6];   // [6890,24]
    float* out = (float*)d_out;

    float *Pt, *JW, *Cpart, *C2, *Jb, *g, *Rs, *Qv;
    cudaGetSymbolAddress((void**)&Pt,    d_Pt);
    cudaGetSymbolAddress((void**)&JW,    d_JW);
    cudaGetSymbolAddress((void**)&Cpart, d_Cpart);
    cudaGetSymbolAddress((void**)&C2,    d_C2);
    cudaGetSymbolAddress((void**)&Jb,    d_Jb);
    cudaGetSymbolAddress((void**)&g,     d_g);
    cudaGetSymbolAddress((void**)&Rs,    d_Rs);
    cudaGetSymbolAddress((void**)&Qv,    d_Qv);

    // 1. gather+transpose basis rows
    k_prep<<<dim3(KPAD/256, M2PAD), 256>>>(posedirs, shapedirs, vtempl, Pt);
    // 2. JW = Jr (x) w
    k_jw<<<(KPAD*N2)/256, 256>>>(Jr, wts, JW);
    // 3. big projection GEMM (split-K)
    k_gemm2<<<dim3(N2/64, M2PAD/64, KSPLIT), 128>>>(Pt, JW, Cpart);
    // 4. reduce partials
    k_reduce<<<(M2*N2 + 255)/256, 256>>>(Cpart, C2);
    // 5. rest-joint basis
    k_jb<<<(3*11*NJ + 255)/256, 256>>>(C2, Jb);
    // 6. rodrigues + features
    k_feat<<<NB, 32>>>(beta, theta, g, Rs);
    // 7. per-batch GEMM Qv = g @ C2
    k_gemm3<<<dim3(27, NB/64), 128>>>(g, C2, Qv);
    // 8. chain + combine -> joints
    k_final<<<NB, 128>>>(beta, Rs, Jb, C2, Qv, out);
}

// round 3
// speedup vs baseline: 1.8467x; 1.8467x over previous
#include <cuda_runtime.h>
#include <cuda_bf16.h>
#include <math.h>
#include <stdint.h>

// ---------------- problem constants ----------------
#define NB     1024
#define NV     6890
#define NJ     24
#define NPOSE  207
#define TROWS  224      // 207 pose + 10 beta + 1 template + 1 ones + 5 pad
#define M2     672      // 3 * TROWS
#define MPAD   768      // 6 * 128
#define N2     576      // jk pairs
#define NPADB  640      // N padded to 5*128
#define KPAD   6912     // vertices padded
#define KSPL   6        // split-K chunks (2 per segment, 3 segments)
#define KCH    3456     // K per chunk
#define TITER  108      // KCH / 32
#define GDIM   224

#define BM 128
#define BN 128
#define BK 32

__constant__ int c_parents[24] = {-1,0,0,0,1,2,3,4,5,6,7,8,9,9,9,12,13,14,16,17,18,19,20,21};

// ---------------- device scratch ----------------
__device__ __align__(16) __nv_bfloat16 d_Ah[MPAD * KPAD];
__device__ __align__(16) __nv_bfloat16 d_Al[MPAD * KPAD];
__device__ __align__(16) __nv_bfloat16 d_Bh[NPADB * KPAD];
__device__ __align__(16) __nv_bfloat16 d_Bl[NPADB * KPAD];
__device__ float d_Jrt[NJ * KPAD];
__device__ float d_wt [NJ * KPAD];
__device__ float d_Cpart[KSPL * MPAD * NPADB];
__device__ float d_C2[M2 * N2];
__device__ float d_Jb[3 * 11 * NJ];
__device__ float d_g[NB * GDIM];
__device__ float d_Rs[NB * NJ * 9];
__device__ float d_Qv[NB * 1728];

// ---------------- helpers ----------------
__device__ __forceinline__ uint32_t smem_u32(const void* p) {
    uint32_t r;
    asm("{ .reg .u64 t; cvta.to.shared.u64 t, %1; cvt.u32.u64 %0, t; }" : "=r"(r) : "l"(p));
    return r;
}

__device__ __forceinline__ void cp_async16(uint32_t saddr, const void* gaddr) {
    asm volatile("cp.async.cg.shared.global [%0], [%1], 16;" :: "r"(saddr), "l"(gaddr) : "memory");
}
__device__ __forceinline__ void cp_commit() {
    asm volatile("cp.async.commit_group;" ::: "memory");
}
__device__ __forceinline__ void cp_wait1() {
    asm volatile("cp.async.wait_group 1;" ::: "memory");
}
__device__ __forceinline__ void cp_wait0() {
    asm volatile("cp.async.wait_group 0;" ::: "memory");
}

__device__ __forceinline__ void ldsm_x4(uint32_t& r0, uint32_t& r1, uint32_t& r2, uint32_t& r3,
                                        uint32_t addr) {
    asm volatile("ldmatrix.sync.aligned.m8n8.x4.shared.b16 {%0,%1,%2,%3}, [%4];"
                 : "=r"(r0), "=r"(r1), "=r"(r2), "=r"(r3) : "r"(addr));
}

__device__ __forceinline__ void mma16816(float& d0, float& d1, float& d2, float& d3,
                                         uint32_t a0, uint32_t a1, uint32_t a2, uint32_t a3,
                                         uint32_t b0, uint32_t b1) {
    asm volatile("mma.sync.aligned.m16n8k16.row.col.f32.bf16.bf16.f32 "
                 "{%0,%1,%2,%3}, {%4,%5,%6,%7}, {%8,%9}, {%0,%1,%2,%3};"
                 : "+f"(d0), "+f"(d1), "+f"(d2), "+f"(d3)
                 : "r"(a0), "r"(a1), "r"(a2), "r"(a3), "r"(b0), "r"(b1));
}

// swizzled byte offset inside a [rows][32 bf16] tile: row r, 16B-chunk c (0..3)
__device__ __forceinline__ uint32_t swz(int r, int c) {
    return (uint32_t)(r * 64 + ((c ^ ((r >> 1) & 3)) << 4));
}

// ---------------- kernel: gather basis rows -> bf16 hi/lo A ----------------
__global__ void k_prepA(const float* __restrict__ posedirs,
                        const float* __restrict__ shapedirs,
                        const float* __restrict__ vtempl,
                        __nv_bfloat16* __restrict__ Ah,
                        __nv_bfloat16* __restrict__ Al)
{
    int v = blockIdx.x * 256 + threadIdx.x;
    int m = blockIdx.y;
    float val = 0.f;
    if (m < M2 && v < NV) {
        int c = m / TROWS;
        int t = m - c * TROWS;
        if (t < NPOSE)             val = posedirs[t * (NV*3) + v*3 + c];
        else if (t < NPOSE+10)     val = shapedirs[(t-NPOSE) * (NV*3) + v*3 + c];
        else if (t == 217)         val = vtempl[v*3 + c];
        else if (t == 218)         val = (c == 0) ? 1.f : 0.f;
    }
    __nv_bfloat16 h = __float2bfloat16(val);
    __nv_bfloat16 l = __float2bfloat16(val - __bfloat162float(h));
    size_t idx = (size_t)m * KPAD + v;
    Ah[idx] = h;
    Al[idx] = l;
}

// ---------------- kernel: transpose Jr, w ----------------
__global__ void k_tr(const float* __restrict__ Jr, const float* __restrict__ w,
                     float* __restrict__ Jrt, float* __restrict__ wt)
{
    int v = blockIdx.x * 256 + threadIdx.x;
    int j = blockIdx.y;
    float a = 0.f, b = 0.f;
    if (v < NV) { a = Jr[v*24 + j]; b = w[v*24 + j]; }
    Jrt[(size_t)j * KPAD + v] = a;
    wt [(size_t)j * KPAD + v] = b;
}

// ---------------- kernel: B[jk][v] = Jr[v,j]*w[v,k] -> bf16 hi/lo ----------------
__global__ void k_prepB(const float* __restrict__ Jrt, const float* __restrict__ wt,
                        __nv_bfloat16* __restrict__ Bh, __nv_bfloat16* __restrict__ Bl)
{
    int v = blockIdx.x * 256 + threadIdx.x;
    int jk = blockIdx.y;                     // 0..639
    float val = 0.f;
    if (jk < N2) {
        int j = jk / 24, k = jk - j * 24;
        val = Jrt[(size_t)j * KPAD + v] * wt[(size_t)k * KPAD + v];
    }
    __nv_bfloat16 h = __float2bfloat16(val);
    __nv_bfloat16 l = __float2bfloat16(val - __bfloat162float(h));
    size_t idx = (size_t)jk * KPAD + v;
    Bh[idx] = h;
    Bl[idx] = l;
}

// ---------------- tensor-core projection GEMM (mma.sync bf16) ----------------
// C[m,n] = sum over 3 segments: Ah@Bh + Ah@Bl + Al@Bh (Al@Bl dropped, ~2^-18)
// split across blockIdx.z: z in [0,6), segment = z/2, half-K per chunk.
__global__ __launch_bounds__(256) void k_mma(const __nv_bfloat16* __restrict__ Ah,
                                             const __nv_bfloat16* __restrict__ Al,
                                             const __nv_bfloat16* __restrict__ Bh,
                                             const __nv_bfloat16* __restrict__ Bl,
                                             float* __restrict__ Cpart)
{
    __shared__ __align__(16) __nv_bfloat16 As[2][BM*BK];
    __shared__ __align__(16) __nv_bfloat16 Bs[2][BN*BK];

    const int tid = threadIdx.x;
    const int wid = tid >> 5, lane = tid & 31;
    const int n0 = blockIdx.x * BN;
    const int m0 = blockIdx.y * BM;
    const int z  = blockIdx.z;
    const int seg = z >> 1;
    const int kbase = (z & 1) * KCH;

    const __nv_bfloat16* Aptr = (seg == 2) ? Al : Ah;
    const __nv_bfloat16* Bptr = (seg == 1) ? Bl : Bh;

    const uint32_t sA[2] = { smem_u32(&As[0][0]), smem_u32(&As[1][0]) };
    const uint32_t sB[2] = { smem_u32(&Bs[0][0]), smem_u32(&Bs[1][0]) };

    const int wm = wid & 1;        // 2 M groups of 64
    const int wn = wid >> 1;       // 4 N groups of 32

    // loader indices: 512 chunks per tile, 2 per thread
    const int cid0 = tid, cid1 = tid + 256;
    const int r0c = cid0 >> 2, c0c = cid0 & 3;
    const int r1c = cid1 >> 2, c1c = cid1 & 3;
    const uint32_t dA0 = swz(r0c, c0c), dA1 = swz(r1c, c1c);

    float acc[4][4][4];
#pragma unroll
    for (int i = 0; i < 4; i++)
#pragma unroll
        for (int j = 0; j < 4; j++)
#pragma unroll
            for (int e = 0; e < 4; e++) acc[i][j][e] = 0.f;

    // ---- stage loader ----
    auto load_stage = [&](int t, int buf) {
        const int kk = kbase + t * BK;
        cp_async16(sA[buf] + dA0, Aptr + (size_t)(m0 + r0c) * KPAD + kk + c0c*8);
        cp_async16(sA[buf] + dA1, Aptr + (size_t)(m0 + r1c) * KPAD + kk + c1c*8);
        cp_async16(sB[buf] + dA0, Bptr + (size_t)(n0 + r0c) * KPAD + kk + c0c*8);
        cp_async16(sB[buf] + dA1, Bptr + (size_t)(n0 + r1c) * KPAD + kk + c1c*8);
        cp_commit();
    };

    load_stage(0, 0);

    for (int t = 0; t < TITER; ++t) {
        const int buf = t & 1;
        if (t + 1 < TITER) { load_stage(t + 1, buf ^ 1); cp_wait1(); }
        else               { cp_wait0(); }
        __syncthreads();

#pragma unroll
        for (int kk = 0; kk < 2; ++kk) {
            uint32_t a[4][4];
#pragma unroll
            for (int i = 0; i < 4; i++) {
                int r = wm*64 + i*16 + (lane & 15);
                int c = kk*2 + (lane >> 4);
                ldsm_x4(a[i][0], a[i][1], a[i][2], a[i][3], sA[buf] + swz(r, c));
            }
            uint32_t bb[4][2];
#pragma unroll
            for (int j2 = 0; j2 < 2; j2++) {
                int n = wn*32 + j2*16 + (lane & 7) + ((lane >> 4) << 3);
                int c = kk*2 + ((lane >> 3) & 1);
                uint32_t q0, q1, q2, q3;
                ldsm_x4(q0, q1, q2, q3, sB[buf] + swz(n, c));
                bb[j2*2+0][0] = q0; bb[j2*2+0][1] = q1;
                bb[j2*2+1][0] = q2; bb[j2*2+1][1] = q3;
            }
#pragma unroll
            for (int i = 0; i < 4; i++)
#pragma unroll
                for (int j = 0; j < 4; j++)
                    mma16816(acc[i][j][0], acc[i][j][1], acc[i][j][2], acc[i][j][3],
                             a[i][0], a[i][1], a[i][2], a[i][3],
                             bb[j][0], bb[j][1]);
        }
        __syncthreads();
    }

    // ---- epilogue ----
    float* cp = Cpart + (size_t)z * (MPAD * NPADB);
#pragma unroll
    for (int i = 0; i < 4; i++) {
        int row = m0 + wm*64 + i*16 + (lane >> 2);
#pragma unroll
        for (int j = 0; j < 4; j++) {
            int col = n0 + wn*32 + j*8 + (lane & 3)*2;
            *(float2*)(cp + (size_t)row * NPADB + col)       = make_float2(acc[i][j][0], acc[i][j][1]);
            *(float2*)(cp + (size_t)(row + 8) * NPADB + col) = make_float2(acc[i][j][2], acc[i][j][3]);
        }
    }
}

// ---------------- reduce split-K partials ----------------
__global__ void k_reduce(const float* __restrict__ Cpart, float* __restrict__ C2)
{
    int idx = blockIdx.x * 256 + threadIdx.x;
    if (idx >= M2 * N2) return;
    int m = idx / N2, n = idx - m * N2;
    float s = 0.f;
#pragma unroll
    for (int p = 0; p < KSPL; p++)
        s += Cpart[(size_t)p * (MPAD*NPADB) + (size_t)m * NPADB + n];
    C2[idx] = s;
}

// ---------------- rest-joint basis ----------------
__global__ void k_jb(const float* __restrict__ C2, float* __restrict__ Jb)
{
    int idx = blockIdx.x * 256 + threadIdx.x;
    if (idx >= 3*11*NJ) return;
    int c = idx / (11*NJ);
    int r = idx - c * (11*NJ);
    int i = r / NJ;
    int j = r - i * NJ;
    const float* row = C2 + (size_t)(c*TROWS + 207 + i) * N2 + j*24;
    float s = 0.f;
#pragma unroll
    for (int k = 0; k < 24; k++) s += row[k];
    Jb[idx] = s;
}

// ---------------- Rodrigues + features ----------------
__global__ void k_feat(const float* __restrict__ beta,
                       const float* __restrict__ theta,
                       float* __restrict__ g, float* __restrict__ Rs)
{
    int b = blockIdx.x;
    int lane = threadIdx.x;
    if (lane < 24) {
        int k = lane;
        float t0 = theta[b*72 + k*3 + 0];
        float t1 = theta[b*72 + k*3 + 1];
        float t2 = theta[b*72 + k*3 + 2];
        float a0 = t0 + 1e-8f, a1 = t1 + 1e-8f, a2 = t2 + 1e-8f;
        float angle = sqrtf(a0*a0 + a1*a1 + a2*a2);
        float inv = 1.f / angle;
        float n0 = t0*inv, n1 = t1*inv, n2 = t2*inv;
        float half = 0.5f * angle;
        float w = cosf(half), s = sinf(half);
        float x = s*n0, y = s*n1, z = s*n2;
        float qn = rsqrtf(w*w + x*x + y*y + z*z);
        w *= qn; x *= qn; y *= qn; z *= qn;
        float rot[9];
        rot[0] = w*w + x*x - y*y - z*z;
        rot[1] = 2.f*(x*y - w*z);
        rot[2] = 2.f*(x*z + w*y);
        rot[3] = 2.f*(x*y + w*z);
        rot[4] = w*w - x*x + y*y - z*z;
        rot[5] = 2.f*(y*z - w*x);
        rot[6] = 2.f*(x*z - w*y);
        rot[7] = 2.f*(y*z + w*x);
        rot[8] = w*w - x*x - y*y + z*z;
        float* rs = Rs + (size_t)(b*24 + k) * 9;
#pragma unroll
        for (int e = 0; e < 9; e++) rs[e] = rot[e];
        if (k > 0) {
            float* gp = g + (size_t)b * GDIM + (k-1)*9;
#pragma unroll
            for (int e = 0; e < 9; e++)
                gp[e] = rot[e] - ((e == 0 || e == 4 || e == 8) ? 1.f : 0.f);
        }
    }
    if (lane < 10)       g[(size_t)b*GDIM + 207 + lane] = beta[b*10 + lane];
    else if (lane == 10) g[(size_t)b*GDIM + 217] = 1.f;
    else if (lane < 17)  g[(size_t)b*GDIM + 207 + lane] = 0.f;
}

// ---------------- per-batch GEMM Qv[b][n] = g[b] @ C2 (fp32, validated) ---------
__global__ __launch_bounds__(128) void k_gemm3(const float* __restrict__ g,
                                               const float* __restrict__ C2,
                                               float* __restrict__ Qv)
{
    __shared__ float As[16][68];
    __shared__ float Bs[16][64];
    const int tid = threadIdx.x;
    const int bx = blockIdx.x;          // 0..26
    const int n0g = bx * 64;
    const int c = bx / 9;
    const int nloc0 = (bx - c*9) * 64;
    const int m0 = blockIdx.y * 64;

    const int tm = tid & 7;
    const int tn = tid >> 3;
    const int lk = tid & 15;
    const int lm = tid >> 4;
    const int ln = tid & 63;
    const int lkb = tid >> 6;

    float acc[8][4];
#pragma unroll
    for (int i = 0; i < 8; i++)
#pragma unroll
        for (int j = 0; j < 4; j++) acc[i][j] = 0.f;

    for (int kt = 0; kt < GDIM/16; ++kt) {
        const int kb = kt * 16;
#pragma unroll
        for (int q = 0; q < 8; q++)
            As[lk][lm + q*8] = g[(size_t)(m0 + lm + q*8) * GDIM + kb + lk];
#pragma unroll
        for (int q = 0; q < 8; q++)
            Bs[lkb + q*2][ln] = C2[(size_t)(c*TROWS + kb + lkb + q*2) * N2 + nloc0 + ln];
        __syncthreads();
#pragma unroll
        for (int kk = 0; kk < 16; kk++) {
            float a[8], b[4];
            *(float4*)&a[0] = *(const float4*)&As[kk][tm*8];
            *(float4*)&a[4] = *(const float4*)&As[kk][tm*8+4];
            *(float4*)&b[0] = *(const float4*)&Bs[kk][tn*4];
#pragma unroll
            for (int i = 0; i < 8; i++)
#pragma unroll
                for (int j = 0; j < 4; j++)
                    acc[i][j] = fmaf(a[i], b[j], acc[i][j]);
        }
        __syncthreads();
    }
#pragma unroll
    for (int i = 0; i < 8; i++) {
        int m = m0 + tm*8 + i;
        *(float4*)&Qv[(size_t)m * 1728 + n0g + tn*4] =
            make_float4(acc[i][0], acc[i][1], acc[i][2], acc[i][3]);
    }
}

// ---------------- kinematic chain + combine ----------------
__global__ __launch_bounds__(128) void k_final(const float* __restrict__ beta,
                                               const float* __restrict__ Rs,
                                               const float* __restrict__ Jb,
                                               const float* __restrict__ C2,
                                               const float* __restrict__ Qv,
                                               float* __restrict__ out)
{
    __shared__ float sR[216];
    __shared__ float sJ[72];
    __shared__ float sG[288];
    __shared__ float sAt[72];
    __shared__ float sBeta[10];
    const int b = blockIdx.x;
    const int tid = threadIdx.x;

    for (int i = tid; i < 216; i += 128) sR[i] = Rs[(size_t)b*216 + i];
    if (tid < 10) sBeta[tid] = beta[b*10 + tid];
    __syncthreads();

    if (tid < 72) {
        int j = tid / 3, c = tid - j*3;
        float v = Jb[(c*11 + 10)*NJ + j];
#pragma unroll
        for (int i = 0; i < 10; i++) v = fmaf(sBeta[i], Jb[(c*11 + i)*NJ + j], v);
        sJ[j*3 + c] = v;
    }
    __syncthreads();

    if (tid < 12) {
        int r = tid >> 2, cc = tid & 3;
        sG[tid] = (cc < 3) ? sR[r*3 + cc] : sJ[r];
        __syncwarp(0x0fff);
        for (int i = 1; i < 24; i++) {
            int p = c_parents[i];
            float v;
            if (cc < 3) {
                v = sG[p*12 + r*4 + 0] * sR[i*9 + 0 + cc]
                  + sG[p*12 + r*4 + 1] * sR[i*9 + 3 + cc]
                  + sG[p*12 + r*4 + 2] * sR[i*9 + 6 + cc];
            } else {
                float tx = sJ[i*3+0] - sJ[p*3+0];
                float ty = sJ[i*3+1] - sJ[p*3+1];
                float tz = sJ[i*3+2] - sJ[p*3+2];
                v = sG[p*12 + r*4 + 0] * tx
                  + sG[p*12 + r*4 + 1] * ty
                  + sG[p*12 + r*4 + 2] * tz
                  + sG[p*12 + r*4 + 3];
            }
            sG[i*12 + r*4 + cc] = v;
            __syncwarp(0x0fff);
        }
    }
    __syncthreads();

    if (tid < 72) {
        int k = tid / 3, c = tid - k*3;
        sAt[k*3 + c] = sG[k*12 + c*4 + 3]
                     - (sG[k*12 + c*4 + 0] * sJ[k*3 + 0]
                      + sG[k*12 + c*4 + 1] * sJ[k*3 + 1]
                      + sG[k*12 + c*4 + 2] * sJ[k*3 + 2]);
    }
    __syncthreads();

    if (tid < 72) {
        int j = tid / 3, c = tid - j*3;
        const float* qb = Qv + (size_t)b * 1728;
        const float* s0 = C2 + 218 * N2;
        float acc = 0.f;
#pragma unroll
        for (int k = 0; k < 24; k++) {
            int jk = j*24 + k;
            acc = fmaf(sG[k*12 + c*4 + 0], qb[jk],        acc);
            acc = fmaf(sG[k*12 + c*4 + 1], qb[576 + jk],  acc);
            acc = fmaf(sG[k*12 + c*4 + 2], qb[1152 + jk], acc);
            acc = fmaf(sAt[k*3 + c],       s0[jk],        acc);
        }
        out[b*72 + j*3 + c] = acc;
    }
}

// ---------------- launcher ----------------
extern "C" void kernel_launch(void* const* d_in, const int* in_sizes, int n_in,
                              void* d_out, int out_size)
{
    const float* beta      = (const float*)d_in[0];
    const float* theta     = (const float*)d_in[1];
    const float* vtempl    = (const float*)d_in[2];
    const float* shapedirs = (const float*)d_in[3];
    const float* posedirs  = (const float*)d_in[4];
    const float* Jr        = (const float*)d_in[5];
    const float* wts       = (const float*)d_in[6];
    float* out = (float*)d_out;

    __nv_bfloat16 *Ah, *Al, *Bh, *Bl;
    float *Jrt, *wt, *Cpart, *C2, *Jb, *g, *Rs, *Qv;
    cudaGetSymbolAddress((void**)&Ah, d_Ah);
    cudaGetSymbolAddress((void**)&Al, d_Al);
    cudaGetSymbolAddress((void**)&Bh, d_Bh);
    cudaGetSymbolAddress((void**)&Bl, d_Bl);
    cudaGetSymbolAddress((void**)&Jrt, d_Jrt);
    cudaGetSymbolAddress((void**)&wt, d_wt);
    cudaGetSymbolAddress((void**)&Cpart, d_Cpart);
    cudaGetSymbolAddress((void**)&C2, d_C2);
    cudaGetSymbolAddress((void**)&Jb, d_Jb);
    cudaGetSymbolAddress((void**)&g, d_g);
    cudaGetSymbolAddress((void**)&Rs, d_Rs);
    cudaGetSymbolAddress((void**)&Qv, d_Qv);

    k_prepA<<<dim3(KPAD/256, MPAD), 256>>>(posedirs, shapedirs, vtempl, Ah, Al);
    k_tr<<<dim3(KPAD/256, NJ), 256>>>(Jr, wts, Jrt, wt);
    k_prepB<<<dim3(KPAD/256, NPADB), 256>>>(Jrt, wt, Bh, Bl);
    k_mma<<<dim3(NPADB/BN, MPAD/BM, KSPL), 256>>>(Ah, Al, Bh, Bl, Cpart);
    k_reduce<<<(M2*N2 + 255)/256, 256>>>(Cpart, C2);
    k_jb<<<(3*11*NJ + 255)/256, 256>>>(C2, Jb);
    k_feat<<<NB, 32>>>(beta, theta, g, Rs);
    k_gemm3<<<dim3(27, NB/64), 128>>>(g, C2, Qv);
    k_final<<<NB, 128>>>(beta, Rs, Jb, C2, Qv, out);
}

// round 4
// speedup vs baseline: 2.2706x; 1.2295x over previous
#include <cuda_runtime.h>
#include <cuda_bf16.h>
#include <math.h>
#include <stdint.h>

// ---------------- problem constants ----------------
#define NB     1024
#define NV     6890
#define NJ     24
#define NPOSE  207
#define TROWS  224      // 207 pose + 10 beta + 1 template + 1 ones + 5 pad
#define M2     672      // 3 * TROWS
#define MPAD   768      // 6 * 128
#define N2     576      // jk pairs (9 * 64)
#define KPAD   6912     // vertices padded
#define GDIM   224

// GEMM tiling
#define BM 128
#define BN 64
#define BK 64
#define NST 4
#define ASZ (BM*BK*2)       // 16384 B
#define BSZ (BN*BK*2)       // 8192 B
#define STG (ASZ+BSZ)       // 24576 B per stage
#define GSMEM (NST*STG)     // 98304 B
#define KITER 27            // 1728 / 64
#define ZSPL 12             // 3 segments x 4 K-subsplits

__constant__ int c_parents[24] = {-1,0,0,0,1,2,3,4,5,6,7,8,9,9,9,12,13,14,16,17,18,19,20,21};

// ---------------- device scratch ----------------
__device__ __align__(16) __nv_bfloat16 d_Ah[MPAD * KPAD];
__device__ __align__(16) __nv_bfloat16 d_Al[MPAD * KPAD];
__device__ __align__(16) __nv_bfloat16 d_Bh[N2 * KPAD];
__device__ __align__(16) __nv_bfloat16 d_Bl[N2 * KPAD];
__device__ float d_Jrt[NJ * KPAD];
__device__ float d_wt [NJ * KPAD];
__device__ float d_Cpart[ZSPL * MPAD * N2];
__device__ float d_C2[M2 * N2];
__device__ float d_Jb[3 * 11 * NJ];
__device__ float d_g[NB * GDIM];
__device__ float d_Rs[NB * NJ * 9];
__device__ float d_Qv[NB * 1728];

// ---------------- helpers ----------------
__device__ __forceinline__ uint32_t smem_u32(const void* p) {
    uint32_t r;
    asm("{ .reg .u64 t; cvta.to.shared.u64 t, %1; cvt.u32.u64 %0, t; }" : "=r"(r) : "l"(p));
    return r;
}
__device__ __forceinline__ void cp_async16(uint32_t saddr, const void* gaddr) {
    asm volatile("cp.async.cg.shared.global [%0], [%1], 16;" :: "r"(saddr), "l"(gaddr) : "memory");
}
__device__ __forceinline__ void cp_commit() {
    asm volatile("cp.async.commit_group;" ::: "memory");
}
__device__ __forceinline__ void ldsm_x4(uint32_t& r0, uint32_t& r1, uint32_t& r2, uint32_t& r3,
                                        uint32_t addr) {
    asm volatile("ldmatrix.sync.aligned.m8n8.x4.shared.b16 {%0,%1,%2,%3}, [%4];"
                 : "=r"(r0), "=r"(r1), "=r"(r2), "=r"(r3) : "r"(addr));
}
__device__ __forceinline__ void mma16816(float& d0, float& d1, float& d2, float& d3,
                                         uint32_t a0, uint32_t a1, uint32_t a2, uint32_t a3,
                                         uint32_t b0, uint32_t b1) {
    asm volatile("mma.sync.aligned.m16n8k16.row.col.f32.bf16.bf16.f32 "
                 "{%0,%1,%2,%3}, {%4,%5,%6,%7}, {%8,%9}, {%0,%1,%2,%3};"
                 : "+f"(d0), "+f"(d1), "+f"(d2), "+f"(d3)
                 : "r"(a0), "r"(a1), "r"(a2), "r"(a3), "r"(b0), "r"(b1));
}
// swizzled byte offset in a [rows][64 bf16] tile: row r, 16B chunk c in 0..7
__device__ __forceinline__ uint32_t swz64(int r, int c) {
    return (uint32_t)(r * 128 + ((c ^ (r & 7)) << 4));
}

// ---------------- kernel: gather basis rows -> bf16 hi/lo A (single pass) -------
__global__ void k_prepA(const float* __restrict__ posedirs,
                        const float* __restrict__ shapedirs,
                        const float* __restrict__ vtempl,
                        __nv_bfloat16* __restrict__ Ah,
                        __nv_bfloat16* __restrict__ Al)
{
    int v = blockIdx.x * 256 + threadIdx.x;  // 0..6911
    int t = blockIdx.y;                      // 0..223
    float val[3] = {0.f, 0.f, 0.f};
    if (v < NV) {
        if (t < NPOSE) {
            val[0] = posedirs[(size_t)t * (NV*3) + v*3 + 0];
            val[1] = posedirs[(size_t)t * (NV*3) + v*3 + 1];
            val[2] = posedirs[(size_t)t * (NV*3) + v*3 + 2];
        } else if (t < NPOSE + 10) {
            val[0] = shapedirs[(size_t)(t-NPOSE) * (NV*3) + v*3 + 0];
            val[1] = shapedirs[(size_t)(t-NPOSE) * (NV*3) + v*3 + 1];
            val[2] = shapedirs[(size_t)(t-NPOSE) * (NV*3) + v*3 + 2];
        } else if (t == 217) {
            val[0] = vtempl[v*3 + 0];
            val[1] = vtempl[v*3 + 1];
            val[2] = vtempl[v*3 + 2];
        } else if (t == 218) {
            val[0] = 1.f;
        }
    }
#pragma unroll
    for (int c = 0; c < 3; ++c) {
        __nv_bfloat16 h = __float2bfloat16(val[c]);
        __nv_bfloat16 l = __float2bfloat16(val[c] - __bfloat162float(h));
        size_t idx = (size_t)(c*TROWS + t) * KPAD + v;
        Ah[idx] = h;
        Al[idx] = l;
    }
    // rows M2..MPAD-1 are never written: device globals are zero-initialized,
    // and nothing writes them -> they stay zero (contribute nothing).
}

// ---------------- kernel: transpose Jr, w ----------------
__global__ void k_tr(const float* __restrict__ Jr, const float* __restrict__ w,
                     float* __restrict__ Jrt, float* __restrict__ wt)
{
    int v = blockIdx.x * 256 + threadIdx.x;
    int j = blockIdx.y;
    float a = 0.f, b = 0.f;
    if (v < NV) { a = Jr[v*24 + j]; b = w[v*24 + j]; }
    Jrt[(size_t)j * KPAD + v] = a;
    wt [(size_t)j * KPAD + v] = b;
}

// ---------------- kernel: B[jk][v] = Jr[v,j]*w[v,k] -> bf16 hi/lo ----------------
__global__ void k_prepB(const float* __restrict__ Jrt, const float* __restrict__ wt,
                        __nv_bfloat16* __restrict__ Bh, __nv_bfloat16* __restrict__ Bl)
{
    int v = blockIdx.x * 256 + threadIdx.x;
    int jk = blockIdx.y;                     // 0..575
    int j = jk / 24, k = jk - j * 24;
    float val = Jrt[(size_t)j * KPAD + v] * wt[(size_t)k * KPAD + v];
    __nv_bfloat16 h = __float2bfloat16(val);
    __nv_bfloat16 l = __float2bfloat16(val - __bfloat162float(h));
    size_t idx = (size_t)jk * KPAD + v;
    Bh[idx] = h;
    Bl[idx] = l;
}

// ---------------- tensor-core projection GEMM (mma.sync bf16, 4-stage) ----------
// C[m,n] = Ah@Bh + Ah@Bl + Al@Bh  (Al@Bl dropped, ~2^-18 relative)
// z = seg*4 + ksub: seg picks operand pair, ksub picks 1728-wide K slice.
__global__ __launch_bounds__(256, 2) void k_mma(const __nv_bfloat16* __restrict__ Ah,
                                                const __nv_bfloat16* __restrict__ Al,
                                                const __nv_bfloat16* __restrict__ Bh,
                                                const __nv_bfloat16* __restrict__ Bl,
                                                float* __restrict__ Cpart)
{
    extern __shared__ char sm[];
    const uint32_t sbase = smem_u32(sm);
    const int tid = threadIdx.x;
    const int lane = tid & 31, wid = tid >> 5;
    const int n0 = blockIdx.x * BN;
    const int m0 = blockIdx.y * BM;
    const int z  = blockIdx.z;
    const int seg = z >> 2;
    const int kbase = (z & 3) * (KITER * BK);

    const __nv_bfloat16* Aptr = (seg == 2) ? Al : Ah;
    const __nv_bfloat16* Bptr = (seg == 1) ? Bl : Bh;

    const int wm = wid & 3;      // 4 M groups of 32
    const int wn = wid >> 2;     // 2 N groups of 32

    const int lr = tid >> 3;     // loader row base (0..31)
    const int lc = tid & 7;      // loader 16B chunk

    auto load_stage = [&](int t) {
        const uint32_t sa = sbase + (uint32_t)(t & 3) * STG;
        const uint32_t sb = sa + ASZ;
        const int kk = kbase + t * BK;
#pragma unroll
        for (int q = 0; q < 4; ++q) {
            int r = lr + q * 32;
            cp_async16(sa + swz64(r, lc), Aptr + (size_t)(m0 + r) * KPAD + kk + lc*8);
        }
#pragma unroll
        for (int q = 0; q < 2; ++q) {
            int r = lr + q * 32;
            cp_async16(sb + swz64(r, lc), Bptr + (size_t)(n0 + r) * KPAD + kk + lc*8);
        }
        cp_commit();
    };

    float acc[2][4][4] = {};

    load_stage(0);
    load_stage(1);
    load_stage(2);

    for (int t = 0; t < KITER; ++t) {
        asm volatile("cp.async.wait_group 2;" ::: "memory");
        __syncthreads();
        if (t + 3 < KITER) load_stage(t + 3);

        const uint32_t sa = sbase + (uint32_t)(t & 3) * STG;
        const uint32_t sb = sa + ASZ;
#pragma unroll
        for (int ks = 0; ks < 4; ++ks) {
            uint32_t a[2][4];
#pragma unroll
            for (int i = 0; i < 2; i++) {
                int r = wm*32 + i*16 + (lane & 15);
                int c = ks*2 + (lane >> 4);
                ldsm_x4(a[i][0], a[i][1], a[i][2], a[i][3], sa + swz64(r, c));
            }
            uint32_t bfr[4][2];
#pragma unroll
            for (int j2 = 0; j2 < 2; j2++) {
                int n = wn*32 + j2*16 + (lane & 7) + ((lane >> 4) << 3);
                int c = ks*2 + ((lane >> 3) & 1);
                uint32_t q0, q1, q2, q3;
                ldsm_x4(q0, q1, q2, q3, sb + swz64(n, c));
                bfr[j2*2+0][0] = q0; bfr[j2*2+0][1] = q1;
                bfr[j2*2+1][0] = q2; bfr[j2*2+1][1] = q3;
            }
#pragma unroll
            for (int i = 0; i < 2; i++)
#pragma unroll
                for (int j = 0; j < 4; j++)
                    mma16816(acc[i][j][0], acc[i][j][1], acc[i][j][2], acc[i][j][3],
                             a[i][0], a[i][1], a[i][2], a[i][3],
                             bfr[j][0], bfr[j][1]);
        }
    }

    // ---- epilogue ----
    float* cp = Cpart + (size_t)z * (MPAD * N2);
#pragma unroll
    for (int i = 0; i < 2; i++) {
        int row = m0 + wm*32 + i*16 + (lane >> 2);
#pragma unroll
        for (int j = 0; j < 4; j++) {
            int col = n0 + wn*32 + j*8 + (lane & 3)*2;
            *(float2*)(cp + (size_t)row * N2 + col)       = make_float2(acc[i][j][0], acc[i][j][1]);
            *(float2*)(cp + (size_t)(row + 8) * N2 + col) = make_float2(acc[i][j][2], acc[i][j][3]);
        }
    }
}

// ---------------- reduce split-K partials ----------------
__global__ void k_reduce(const float* __restrict__ Cpart, float* __restrict__ C2)
{
    int idx = blockIdx.x * 256 + threadIdx.x;
    if (idx >= M2 * N2) return;
    int m = idx / N2, n = idx - m * N2;
    float s = 0.f;
#pragma unroll
    for (int p = 0; p < ZSPL; p++)
        s += Cpart[(size_t)p * (MPAD*N2) + (size_t)m * N2 + n];
    C2[idx] = s;
}

// ---------------- rest-joint basis ----------------
__global__ void k_jb(const float* __restrict__ C2, float* __restrict__ Jb)
{
    int idx = blockIdx.x * 256 + threadIdx.x;
    if (idx >= 3*11*NJ) return;
    int c = idx / (11*NJ);
    int r = idx - c * (11*NJ);
    int i = r / NJ;
    int j = r - i * NJ;
    const float* row = C2 + (size_t)(c*TROWS + 207 + i) * N2 + j*24;
    float s = 0.f;
#pragma unroll
    for (int k = 0; k < 24; k++) s += row[k];
    Jb[idx] = s;
}

// ---------------- Rodrigues + features ----------------
__global__ void k_feat(const float* __restrict__ beta,
                       const float* __restrict__ theta,
                       float* __restrict__ g, float* __restrict__ Rs)
{
    int b = blockIdx.x;
    int lane = threadIdx.x;
    if (lane < 24) {
        int k = lane;
        float t0 = theta[b*72 + k*3 + 0];
        float t1 = theta[b*72 + k*3 + 1];
        float t2 = theta[b*72 + k*3 + 2];
        float a0 = t0 + 1e-8f, a1 = t1 + 1e-8f, a2 = t2 + 1e-8f;
        float angle = sqrtf(a0*a0 + a1*a1 + a2*a2);
        float inv = 1.f / angle;
        float n0 = t0*inv, n1 = t1*inv, n2 = t2*inv;
        float half = 0.5f * angle;
        float w = cosf(half), s = sinf(half);
        float x = s*n0, y = s*n1, z = s*n2;
        float qn = rsqrtf(w*w + x*x + y*y + z*z);
        w *= qn; x *= qn; y *= qn; z *= qn;
        float rot[9];
        rot[0] = w*w + x*x - y*y - z*z;
        rot[1] = 2.f*(x*y - w*z);
        rot[2] = 2.f*(x*z + w*y);
        rot[3] = 2.f*(x*y + w*z);
        rot[4] = w*w - x*x + y*y - z*z;
        rot[5] = 2.f*(y*z - w*x);
        rot[6] = 2.f*(x*z - w*y);
        rot[7] = 2.f*(y*z + w*x);
        rot[8] = w*w - x*x - y*y + z*z;
        float* rs = Rs + (size_t)(b*24 + k) * 9;
#pragma unroll
        for (int e = 0; e < 9; e++) rs[e] = rot[e];
        if (k > 0) {
            float* gp = g + (size_t)b * GDIM + (k-1)*9;
#pragma unroll
            for (int e = 0; e < 9; e++)
                gp[e] = rot[e] - ((e == 0 || e == 4 || e == 8) ? 1.f : 0.f);
        }
    }
    if (lane < 10)       g[(size_t)b*GDIM + 207 + lane] = beta[b*10 + lane];
    else if (lane == 10) g[(size_t)b*GDIM + 217] = 1.f;
    else if (lane < 17)  g[(size_t)b*GDIM + 207 + lane] = 0.f;
}

// ---------------- per-batch GEMM Qv[b][n] = g[b] @ C2 (fp32) ----------------
__global__ __launch_bounds__(128) void k_gemm3(const float* __restrict__ g,
                                               const float* __restrict__ C2,
                                               float* __restrict__ Qv)
{
    __shared__ float As[16][68];
    __shared__ float Bs[16][64];
    const int tid = threadIdx.x;
    const int bx = blockIdx.x;          // 0..26
    const int n0g = bx * 64;
    const int c = bx / 9;
    const int nloc0 = (bx - c*9) * 64;
    const int m0 = blockIdx.y * 64;

    const int tm = tid & 7;
    const int tn = tid >> 3;
    const int lk = tid & 15;
    const int lm = tid >> 4;
    const int ln = tid & 63;
    const int lkb = tid >> 6;

    float acc[8][4];
#pragma unroll
    for (int i = 0; i < 8; i++)
#pragma unroll
        for (int j = 0; j < 4; j++) acc[i][j] = 0.f;

    for (int kt = 0; kt < GDIM/16; ++kt) {
        const int kb = kt * 16;
#pragma unroll
        for (int q = 0; q < 8; q++)
            As[lk][lm + q*8] = g[(size_t)(m0 + lm + q*8) * GDIM + kb + lk];
#pragma unroll
        for (int q = 0; q < 8; q++)
            Bs[lkb + q*2][ln] = C2[(size_t)(c*TROWS + kb + lkb + q*2) * N2 + nloc0 + ln];
        __syncthreads();
#pragma unroll
        for (int kk = 0; kk < 16; kk++) {
            float a[8], b[4];
            *(float4*)&a[0] = *(const float4*)&As[kk][tm*8];
            *(float4*)&a[4] = *(const float4*)&As[kk][tm*8+4];
            *(float4*)&b[0] = *(const float4*)&Bs[kk][tn*4];
#pragma unroll
            for (int i = 0; i < 8; i++)
#pragma unroll
                for (int j = 0; j < 4; j++)
                    acc[i][j] = fmaf(a[i], b[j], acc[i][j]);
        }
        __syncthreads();
    }
#pragma unroll
    for (int i = 0; i < 8; i++) {
        int m = m0 + tm*8 + i;
        *(float4*)&Qv[(size_t)m * 1728 + n0g + tn*4] =
            make_float4(acc[i][0], acc[i][1], acc[i][2], acc[i][3]);
    }
}

// ---------------- kinematic chain + combine ----------------
__global__ __launch_bounds__(128) void k_final(const float* __restrict__ beta,
                                               const float* __restrict__ Rs,
                                               const float* __restrict__ Jb,
                                               const float* __restrict__ C2,
                                               const float* __restrict__ Qv,
                                               float* __restrict__ out)
{
    __shared__ float sR[216];
    __shared__ float sJ[72];
    __shared__ float sG[288];
    __shared__ float sAt[72];
    __shared__ float sBeta[10];
    const int b = blockIdx.x;
    const int tid = threadIdx.x;

    for (int i = tid; i < 216; i += 128) sR[i] = Rs[(size_t)b*216 + i];
    if (tid < 10) sBeta[tid] = beta[b*10 + tid];
    __syncthreads();

    if (tid < 72) {
        int j = tid / 3, c = tid - j*3;
        float v = Jb[(c*11 + 10)*NJ + j];
#pragma unroll
        for (int i = 0; i < 10; i++) v = fmaf(sBeta[i], Jb[(c*11 + i)*NJ + j], v);
        sJ[j*3 + c] = v;
    }
    __syncthreads();

    if (tid < 12) {
        int r = tid >> 2, cc = tid & 3;
        sG[tid] = (cc < 3) ? sR[r*3 + cc] : sJ[r];
        __syncwarp(0x0fff);
        for (int i = 1; i < 24; i++) {
            int p = c_parents[i];
            float v;
            if (cc < 3) {
                v = sG[p*12 + r*4 + 0] * sR[i*9 + 0 + cc]
                  + sG[p*12 + r*4 + 1] * sR[i*9 + 3 + cc]
                  + sG[p*12 + r*4 + 2] * sR[i*9 + 6 + cc];
            } else {
                float tx = sJ[i*3+0] - sJ[p*3+0];
                float ty = sJ[i*3+1] - sJ[p*3+1];
                float tz = sJ[i*3+2] - sJ[p*3+2];
                v = sG[p*12 + r*4 + 0] * tx
                  + sG[p*12 + r*4 + 1] * ty
                  + sG[p*12 + r*4 + 2] * tz
                  + sG[p*12 + r*4 + 3];
            }
            sG[i*12 + r*4 + cc] = v;
            __syncwarp(0x0fff);
        }
    }
    __syncthreads();

    if (tid < 72) {
        int k = tid / 3, c = tid - k*3;
        sAt[k*3 + c] = sG[k*12 + c*4 + 3]
                     - (sG[k*12 + c*4 + 0] * sJ[k*3 + 0]
                      + sG[k*12 + c*4 + 1] * sJ[k*3 + 1]
                      + sG[k*12 + c*4 + 2] * sJ[k*3 + 2]);
    }
    __syncthreads();

    if (tid < 72) {
        int j = tid / 3, c = tid - j*3;
        const float* qb = Qv + (size_t)b * 1728;
        const float* s0 = C2 + 218 * N2;
        float acc = 0.f;
#pragma unroll
        for (int k = 0; k < 24; k++) {
            int jk = j*24 + k;
            acc = fmaf(sG[k*12 + c*4 + 0], qb[jk],        acc);
            acc = fmaf(sG[k*12 + c*4 + 1], qb[576 + jk],  acc);
            acc = fmaf(sG[k*12 + c*4 + 2], qb[1152 + jk], acc);
            acc = fmaf(sAt[k*3 + c],       s0[jk],        acc);
        }
        out[b*72 + j*3 + c] = acc;
    }
}

// ---------------- launcher ----------------
extern "C" void kernel_launch(void* const* d_in, const int* in_sizes, int n_in,
                              void* d_out, int out_size)
{
    const float* beta      = (const float*)d_in[0];
    const float* theta     = (const float*)d_in[1];
    const float* vtempl    = (const float*)d_in[2];
    const float* shapedirs = (const float*)d_in[3];
    const float* posedirs  = (const float*)d_in[4];
    const float* Jr        = (const float*)d_in[5];
    const float* wts       = (const float*)d_in[6];
    float* out = (float*)d_out;

    __nv_bfloat16 *Ah, *Al, *Bh, *Bl;
    float *Jrt, *wt, *Cpart, *C2, *Jb, *g, *Rs, *Qv;
    cudaGetSymbolAddress((void**)&Ah, d_Ah);
    cudaGetSymbolAddress((void**)&Al, d_Al);
    cudaGetSymbolAddress((void**)&Bh, d_Bh);
    cudaGetSymbolAddress((void**)&Bl, d_Bl);
    cudaGetSymbolAddress((void**)&Jrt, d_Jrt);
    cudaGetSymbolAddress((void**)&wt, d_wt);
    cudaGetSymbolAddress((void**)&Cpart, d_Cpart);
    cudaGetSymbolAddress((void**)&C2, d_C2);
    cudaGetSymbolAddress((void**)&Jb, d_Jb);
    cudaGetSymbolAddress((void**)&g, d_g);
    cudaGetSymbolAddress((void**)&Rs, d_Rs);
    cudaGetSymbolAddress((void**)&Qv, d_Qv);

    cudaFuncSetAttribute(k_mma, cudaFuncAttributeMaxDynamicSharedMemorySize, GSMEM);

    k_prepA<<<dim3(KPAD/256, TROWS), 256>>>(posedirs, shapedirs, vtempl, Ah, Al);
    k_tr<<<dim3(KPAD/256, NJ), 256>>>(Jr, wts, Jrt, wt);
    k_prepB<<<dim3(KPAD/256, N2), 256>>>(Jrt, wt, Bh, Bl);
    k_mma<<<dim3(N2/BN, MPAD/BM, ZSPL), 256, GSMEM>>>(Ah, Al, Bh, Bl, Cpart);
    k_reduce<<<(M2*N2 + 255)/256, 256>>>(Cpart, C2);
    k_jb<<<(3*11*NJ + 255)/256, 256>>>(C2, Jb);
    k_feat<<<NB, 32>>>(beta, theta, g, Rs);
    k_gemm3<<<dim3(27, NB/64), 128>>>(g, C2, Qv);
    k_final<<<NB, 128>>>(beta, Rs, Jb, C2, Qv, out);
}

// round 5
// speedup vs baseline: 2.5898x; 1.1406x over previous
#include <cuda_runtime.h>
#include <cuda_bf16.h>
#include <math.h>
#include <stdint.h>

// ---------------- problem constants ----------------
#define NB     1024
#define NV     6890
#define NJ     24
#define NPOSE  207
#define TROWS  224
#define M2     672      // 3 * TROWS
#define MPAD   768
#define N2     576      // jk pairs
#define NQ     1728     // 3 * 576
#define KPAD   6912
#define GDIM   224

// big GEMM tiling
#define BM 128
#define BN 64
#define BK 32
#define NST 4
#define ASZ (BM*BK*2)       // 8192 B
#define BSZ (BN*BK*2)       // 4096 B
#define STG (ASZ+BSZ)       // 12288 B
#define GSMEM (NST*STG)     // 49152 B
#define ZSPL 12             // 3 segments x 4 K-subsplits
#define KITER 54            // 1728 / 32 per subsplit

__constant__ int c_parents[24] = {-1,0,0,0,1,2,3,4,5,6,7,8,9,9,9,12,13,14,16,17,18,19,20,21};

// ---------------- device scratch ----------------
__device__ __align__(16) __nv_bfloat16 d_Ah[MPAD * KPAD];
__device__ __align__(16) __nv_bfloat16 d_Al[MPAD * KPAD];
__device__ __align__(16) __nv_bfloat16 d_Bh[N2 * KPAD];
__device__ __align__(16) __nv_bfloat16 d_Bl[N2 * KPAD];
__device__ float d_Jrt[NJ * KPAD];
__device__ float d_wt [NJ * KPAD];
__device__ float d_Cpart[ZSPL * MPAD * N2];
__device__ float d_C2[M2 * N2];
__device__ __align__(16) __nv_bfloat16 d_Bth[NQ * GDIM];   // C2 transposed hi
__device__ __align__(16) __nv_bfloat16 d_Btl[NQ * GDIM];   // C2 transposed lo
__device__ float d_Jb[3 * 11 * NJ];
__device__ __align__(16) __nv_bfloat16 d_gh[NB * GDIM];
__device__ __align__(16) __nv_bfloat16 d_gl[NB * GDIM];
__device__ float d_Rs[NB * NJ * 9];
__device__ float d_Qv[NB * NQ];

// ---------------- helpers ----------------
__device__ __forceinline__ uint32_t smem_u32(const void* p) {
    uint32_t r;
    asm("{ .reg .u64 t; cvta.to.shared.u64 t, %1; cvt.u32.u64 %0, t; }" : "=r"(r) : "l"(p));
    return r;
}
__device__ __forceinline__ void cp_async16(uint32_t saddr, const void* gaddr) {
    asm volatile("cp.async.cg.shared.global [%0], [%1], 16;" :: "r"(saddr), "l"(gaddr) : "memory");
}
__device__ __forceinline__ void cp_commit() {
    asm volatile("cp.async.commit_group;" ::: "memory");
}
__device__ __forceinline__ void ldsm_x4(uint32_t& r0, uint32_t& r1, uint32_t& r2, uint32_t& r3,
                                        uint32_t addr) {
    asm volatile("ldmatrix.sync.aligned.m8n8.x4.shared.b16 {%0,%1,%2,%3}, [%4];"
                 : "=r"(r0), "=r"(r1), "=r"(r2), "=r"(r3) : "r"(addr));
}
__device__ __forceinline__ void mma16816(float& d0, float& d1, float& d2, float& d3,
                                         uint32_t a0, uint32_t a1, uint32_t a2, uint32_t a3,
                                         uint32_t b0, uint32_t b1) {
    asm volatile("mma.sync.aligned.m16n8k16.row.col.f32.bf16.bf16.f32 "
                 "{%0,%1,%2,%3}, {%4,%5,%6,%7}, {%8,%9}, {%0,%1,%2,%3};"
                 : "+f"(d0), "+f"(d1), "+f"(d2), "+f"(d3)
                 : "r"(a0), "r"(a1), "r"(a2), "r"(a3), "r"(b0), "r"(b1));
}
// swizzled byte offset in a [rows][32 bf16] tile: row r, 16B chunk c in 0..3
__device__ __forceinline__ uint32_t swz32(int r, int c) {
    return (uint32_t)(r * 64 + ((c ^ ((r >> 1) & 3)) << 4));
}

// ---------------- prep: gather basis rows (A) + transpose Jr/w ----------------
__global__ void k_prep(const float* __restrict__ posedirs,
                       const float* __restrict__ shapedirs,
                       const float* __restrict__ vtempl,
                       const float* __restrict__ Jr, const float* __restrict__ w,
                       __nv_bfloat16* __restrict__ Ah, __nv_bfloat16* __restrict__ Al,
                       float* __restrict__ Jrt, float* __restrict__ wt)
{
    int v = blockIdx.x * 256 + threadIdx.x;
    int y = blockIdx.y;
    if (y < TROWS) {
        int t = y;
        float val[3] = {0.f, 0.f, 0.f};
        if (v < NV) {
            if (t < NPOSE) {
                val[0] = posedirs[(size_t)t * (NV*3) + v*3 + 0];
                val[1] = posedirs[(size_t)t * (NV*3) + v*3 + 1];
                val[2] = posedirs[(size_t)t * (NV*3) + v*3 + 2];
            } else if (t < NPOSE + 10) {
                val[0] = shapedirs[(size_t)(t-NPOSE) * (NV*3) + v*3 + 0];
                val[1] = shapedirs[(size_t)(t-NPOSE) * (NV*3) + v*3 + 1];
                val[2] = shapedirs[(size_t)(t-NPOSE) * (NV*3) + v*3 + 2];
            } else if (t == 217) {
                val[0] = vtempl[v*3 + 0];
                val[1] = vtempl[v*3 + 1];
                val[2] = vtempl[v*3 + 2];
            } else if (t == 218) {
                val[0] = 1.f;
            }
        }
#pragma unroll
        for (int c = 0; c < 3; ++c) {
            __nv_bfloat16 h = __float2bfloat16(val[c]);
            __nv_bfloat16 l = __float2bfloat16(val[c] - __bfloat162float(h));
            size_t idx = (size_t)(c*TROWS + t) * KPAD + v;
            Ah[idx] = h;
            Al[idx] = l;
        }
    } else {
        int j = y - TROWS;
        float a = 0.f, b = 0.f;
        if (v < NV) { a = Jr[v*24 + j]; b = w[v*24 + j]; }
        Jrt[(size_t)j * KPAD + v] = a;
        wt [(size_t)j * KPAD + v] = b;
    }
}

// ---------------- B[jk][v] = Jr[v,j]*w[v,k] -> bf16 hi/lo ----------------
__global__ void k_prepB(const float* __restrict__ Jrt, const float* __restrict__ wt,
                        __nv_bfloat16* __restrict__ Bh, __nv_bfloat16* __restrict__ Bl)
{
    int v = blockIdx.x * 256 + threadIdx.x;
    int jk = blockIdx.y;
    int j = jk / 24, k = jk - j * 24;
    float val = Jrt[(size_t)j * KPAD + v] * wt[(size_t)k * KPAD + v];
    __nv_bfloat16 h = __float2bfloat16(val);
    __nv_bfloat16 l = __float2bfloat16(val - __bfloat162float(h));
    size_t idx = (size_t)jk * KPAD + v;
    Bh[idx] = h;
    Bl[idx] = l;
}

// ---------------- big projection GEMM (bf16 mma, 3 CTA/SM) ----------------
__global__ __launch_bounds__(256, 3) void k_mma(const __nv_bfloat16* __restrict__ Ah,
                                                const __nv_bfloat16* __restrict__ Al,
                                                const __nv_bfloat16* __restrict__ Bh,
                                                const __nv_bfloat16* __restrict__ Bl,
                                                float* __restrict__ Cpart)
{
    extern __shared__ char sm[];
    const uint32_t sbase = smem_u32(sm);
    const int tid = threadIdx.x;
    const int lane = tid & 31, wid = tid >> 5;
    const int n0 = blockIdx.x * BN;
    const int m0 = blockIdx.y * BM;
    const int z  = blockIdx.z;
    const int seg = z >> 2;
    const int kbase = (z & 3) * (KITER * BK);

    const __nv_bfloat16* Aptr = (seg == 2) ? Al : Ah;
    const __nv_bfloat16* Bptr = (seg == 1) ? Bl : Bh;

    const int wm = wid & 3;
    const int wn = wid >> 2;

    const int lrA0 = tid >> 2, lcA0 = tid & 3;            // A chunk 0
    const int lrA1 = (tid + 256) >> 2, lcA1 = tid & 3;    // A chunk 1

    auto load_stage = [&](int t) {
        const uint32_t sa = sbase + (uint32_t)(t & 3) * STG;
        const uint32_t sb = sa + ASZ;
        const int kk = kbase + t * BK;
        cp_async16(sa + swz32(lrA0, lcA0), Aptr + (size_t)(m0 + lrA0) * KPAD + kk + lcA0*8);
        cp_async16(sa + swz32(lrA1, lcA1), Aptr + (size_t)(m0 + lrA1) * KPAD + kk + lcA1*8);
        cp_async16(sb + swz32(lrA0, lcA0), Bptr + (size_t)(n0 + lrA0) * KPAD + kk + lcA0*8);
        cp_commit();
    };

    float acc[2][4][4] = {};

    load_stage(0);
    load_stage(1);
    load_stage(2);

    for (int t = 0; t < KITER; ++t) {
        asm volatile("cp.async.wait_group 2;" ::: "memory");
        __syncthreads();
        if (t + 3 < KITER) load_stage(t + 3);

        const uint32_t sa = sbase + (uint32_t)(t & 3) * STG;
        const uint32_t sb = sa + ASZ;
#pragma unroll
        for (int ks = 0; ks < 2; ++ks) {
            uint32_t a[2][4];
#pragma unroll
            for (int i = 0; i < 2; i++) {
                int r = wm*32 + i*16 + (lane & 15);
                int c = ks*2 + (lane >> 4);
                ldsm_x4(a[i][0], a[i][1], a[i][2], a[i][3], sa + swz32(r, c));
            }
            uint32_t bfr[4][2];
#pragma unroll
            for (int j2 = 0; j2 < 2; j2++) {
                int n = wn*32 + j2*16 + (lane & 7) + ((lane >> 4) << 3);
                int c = ks*2 + ((lane >> 3) & 1);
                uint32_t q0, q1, q2, q3;
                ldsm_x4(q0, q1, q2, q3, sb + swz32(n, c));
                bfr[j2*2+0][0] = q0; bfr[j2*2+0][1] = q1;
                bfr[j2*2+1][0] = q2; bfr[j2*2+1][1] = q3;
            }
#pragma unroll
            for (int i = 0; i < 2; i++)
#pragma unroll
                for (int j = 0; j < 4; j++)
                    mma16816(acc[i][j][0], acc[i][j][1], acc[i][j][2], acc[i][j][3],
                             a[i][0], a[i][1], a[i][2], a[i][3],
                             bfr[j][0], bfr[j][1]);
        }
    }

    float* cp = Cpart + (size_t)z * (MPAD * N2);
#pragma unroll
    for (int i = 0; i < 2; i++) {
        int row = m0 + wm*32 + i*16 + (lane >> 2);
#pragma unroll
        for (int j = 0; j < 4; j++) {
            int col = n0 + wn*32 + j*8 + (lane & 3)*2;
            *(float2*)(cp + (size_t)row * N2 + col)       = make_float2(acc[i][j][0], acc[i][j][1]);
            *(float2*)(cp + (size_t)(row + 8) * N2 + col) = make_float2(acc[i][j][2], acc[i][j][3]);
        }
    }
}

// ---------------- reduce split-K + emit transposed bf16 hi/lo C2 ----------------
__global__ void k_reduce(const float* __restrict__ Cpart, float* __restrict__ C2,
                         __nv_bfloat16* __restrict__ Bth, __nv_bfloat16* __restrict__ Btl)
{
    __shared__ float s[32][33];
    const int n0 = blockIdx.x * 32;
    const int m0 = blockIdx.y * 32;
    const int tx = threadIdx.x, ty = threadIdx.y;

#pragma unroll
    for (int q = 0; q < 4; ++q) {
        int m = m0 + ty + q*8;
        float sum = 0.f;
#pragma unroll
        for (int p = 0; p < ZSPL; p++)
            sum += Cpart[(size_t)p * (MPAD*N2) + (size_t)m * N2 + n0 + tx];
        C2[(size_t)m * N2 + n0 + tx] = sum;
        s[ty + q*8][tx] = sum;
    }
    __syncthreads();

    const int c  = m0 / TROWS;          // 224 = 7*32, tiles never straddle channels
    const int t0 = m0 - c * TROWS;
#pragma unroll
    for (int q = 0; q < 4; ++q) {
        int n = n0 + ty + q*8;
        float v = s[tx][ty + q*8];
        __nv_bfloat16 h = __float2bfloat16(v);
        __nv_bfloat16 l = __float2bfloat16(v - __bfloat162float(h));
        size_t o = (size_t)(c*N2 + n) * GDIM + t0 + tx;
        Bth[o] = h;
        Btl[o] = l;
    }
}

// ---------------- Rodrigues + features (bf16 hi/lo) + rest-joint basis ---------
__global__ void k_featjb(const float* __restrict__ beta,
                         const float* __restrict__ theta,
                         const float* __restrict__ C2,
                         __nv_bfloat16* __restrict__ gh, __nv_bfloat16* __restrict__ gl,
                         float* __restrict__ Rs, float* __restrict__ Jb)
{
    int b = blockIdx.x;
    int lane = threadIdx.x;
    if (b == NB) {
        // rest-joint basis block
        for (int idx = lane; idx < 3*11*NJ; idx += 128) {
            int c = idx / (11*NJ);
            int r = idx - c * (11*NJ);
            int i = r / NJ;
            int j = r - i * NJ;
            const float* row = C2 + (size_t)(c*TROWS + 207 + i) * N2 + j*24;
            float s = 0.f;
#pragma unroll
            for (int k = 0; k < 24; k++) s += row[k];
            Jb[idx] = s;
        }
        return;
    }
    auto wr = [&](int idx, float v) {
        __nv_bfloat16 h = __float2bfloat16(v);
        __nv_bfloat16 l = __float2bfloat16(v - __bfloat162float(h));
        gh[(size_t)b*GDIM + idx] = h;
        gl[(size_t)b*GDIM + idx] = l;
    };
    if (lane < 24) {
        int k = lane;
        float t0 = theta[b*72 + k*3 + 0];
        float t1 = theta[b*72 + k*3 + 1];
        float t2 = theta[b*72 + k*3 + 2];
        float a0 = t0 + 1e-8f, a1 = t1 + 1e-8f, a2 = t2 + 1e-8f;
        float angle = sqrtf(a0*a0 + a1*a1 + a2*a2);
        float inv = 1.f / angle;
        float n0 = t0*inv, n1 = t1*inv, n2 = t2*inv;
        float half = 0.5f * angle;
        float w = cosf(half), s = sinf(half);
        float x = s*n0, y = s*n1, z = s*n2;
        float qn = rsqrtf(w*w + x*x + y*y + z*z);
        w *= qn; x *= qn; y *= qn; z *= qn;
        float rot[9];
        rot[0] = w*w + x*x - y*y - z*z;
        rot[1] = 2.f*(x*y - w*z);
        rot[2] = 2.f*(x*z + w*y);
        rot[3] = 2.f*(x*y + w*z);
        rot[4] = w*w - x*x + y*y - z*z;
        rot[5] = 2.f*(y*z - w*x);
        rot[6] = 2.f*(x*z - w*y);
        rot[7] = 2.f*(y*z + w*x);
        rot[8] = w*w - x*x - y*y + z*z;
        float* rs = Rs + (size_t)(b*24 + k) * 9;
#pragma unroll
        for (int e = 0; e < 9; e++) rs[e] = rot[e];
        if (k > 0) {
#pragma unroll
            for (int e = 0; e < 9; e++)
                wr((k-1)*9 + e, rot[e] - ((e == 0 || e == 4 || e == 8) ? 1.f : 0.f));
        }
    }
    if (lane < 10)       wr(207 + lane, beta[b*10 + lane]);
    else if (lane == 10) wr(217, 1.f);
    else if (lane < 17)  wr(207 + lane, 0.f);
}

// ---------------- per-batch GEMM Qv = g @ C2t^T (bf16 mma, 3 passes) ------------
#define G3ITER 21     // 3 segments x 224/32
__global__ __launch_bounds__(256) void k_gemm3m(const __nv_bfloat16* __restrict__ gh,
                                                const __nv_bfloat16* __restrict__ gl,
                                                const __nv_bfloat16* __restrict__ Bth,
                                                const __nv_bfloat16* __restrict__ Btl,
                                                float* __restrict__ Qv)
{
    extern __shared__ char sm[];
    const uint32_t sbase = smem_u32(sm);
    const int tid = threadIdx.x;
    const int lane = tid & 31, wid = tid >> 5;
    const int n0 = blockIdx.x * BN;
    const int m0 = blockIdx.y * BM;

    const int wm = wid & 3;
    const int wn = wid >> 2;
    const int lrA0 = tid >> 2, lcA0 = tid & 3;
    const int lrA1 = (tid + 256) >> 2;

    auto load_stage = [&](int t) {
        const int seg = t / 7;
        const int kk = (t - seg*7) * BK;
        const __nv_bfloat16* Aptr = (seg == 2) ? gl : gh;
        const __nv_bfloat16* Bptr = (seg == 1) ? Btl : Bth;
        const uint32_t sa = sbase + (uint32_t)(t & 3) * STG;
        const uint32_t sb = sa + ASZ;
        cp_async16(sa + swz32(lrA0, lcA0), Aptr + (size_t)(m0 + lrA0) * GDIM + kk + lcA0*8);
        cp_async16(sa + swz32(lrA1, lcA0), Aptr + (size_t)(m0 + lrA1) * GDIM + kk + lcA0*8);
        cp_async16(sb + swz32(lrA0, lcA0), Bptr + (size_t)(n0 + lrA0) * GDIM + kk + lcA0*8);
        cp_commit();
    };

    float acc[2][4][4] = {};

    load_stage(0);
    load_stage(1);
    load_stage(2);

    for (int t = 0; t < G3ITER; ++t) {
        asm volatile("cp.async.wait_group 2;" ::: "memory");
        __syncthreads();
        if (t + 3 < G3ITER) load_stage(t + 3);

        const uint32_t sa = sbase + (uint32_t)(t & 3) * STG;
        const uint32_t sb = sa + ASZ;
#pragma unroll
        for (int ks = 0; ks < 2; ++ks) {
            uint32_t a[2][4];
#pragma unroll
            for (int i = 0; i < 2; i++) {
                int r = wm*32 + i*16 + (lane & 15);
                int c = ks*2 + (lane >> 4);
                ldsm_x4(a[i][0], a[i][1], a[i][2], a[i][3], sa + swz32(r, c));
            }
            uint32_t bfr[4][2];
#pragma unroll
            for (int j2 = 0; j2 < 2; j2++) {
                int n = wn*32 + j2*16 + (lane & 7) + ((lane >> 4) << 3);
                int c = ks*2 + ((lane >> 3) & 1);
                uint32_t q0, q1, q2, q3;
                ldsm_x4(q0, q1, q2, q3, sb + swz32(n, c));
                bfr[j2*2+0][0] = q0; bfr[j2*2+0][1] = q1;
                bfr[j2*2+1][0] = q2; bfr[j2*2+1][1] = q3;
            }
#pragma unroll
            for (int i = 0; i < 2; i++)
#pragma unroll
                for (int j = 0; j < 4; j++)
                    mma16816(acc[i][j][0], acc[i][j][1], acc[i][j][2], acc[i][j][3],
                             a[i][0], a[i][1], a[i][2], a[i][3],
                             bfr[j][0], bfr[j][1]);
        }
    }

#pragma unroll
    for (int i = 0; i < 2; i++) {
        int row = m0 + wm*32 + i*16 + (lane >> 2);
#pragma unroll
        for (int j = 0; j < 4; j++) {
            int col = n0 + wn*32 + j*8 + (lane & 3)*2;
            *(float2*)(Qv + (size_t)row * NQ + col)       = make_float2(acc[i][j][0], acc[i][j][1]);
            *(float2*)(Qv + (size_t)(row + 8) * NQ + col) = make_float2(acc[i][j][2], acc[i][j][3]);
        }
    }
}

// ---------------- kinematic chain + combine ----------------
__global__ __launch_bounds__(128) void k_final(const float* __restrict__ beta,
                                               const float* __restrict__ Rs,
                                               const float* __restrict__ Jb,
                                               const float* __restrict__ C2,
                                               const float* __restrict__ Qv,
                                               float* __restrict__ out)
{
    __shared__ float sR[216];
    __shared__ float sJ[72];
    __shared__ float sG[288];
    __shared__ float sAt[72];
    __shared__ float sBeta[10];
    const int b = blockIdx.x;
    const int tid = threadIdx.x;

    for (int i = tid; i < 216; i += 128) sR[i] = Rs[(size_t)b*216 + i];
    if (tid < 10) sBeta[tid] = beta[b*10 + tid];
    __syncthreads();

    if (tid < 72) {
        int j = tid / 3, c = tid - j*3;
        float v = Jb[(c*11 + 10)*NJ + j];
#pragma unroll
        for (int i = 0; i < 10; i++) v = fmaf(sBeta[i], Jb[(c*11 + i)*NJ + j], v);
        sJ[j*3 + c] = v;
    }
    __syncthreads();

    if (tid < 12) {
        int r = tid >> 2, cc = tid & 3;
        sG[tid] = (cc < 3) ? sR[r*3 + cc] : sJ[r];
        __syncwarp(0x0fff);
        for (int i = 1; i < 24; i++) {
            int p = c_parents[i];
            float v;
            if (cc < 3) {
                v = sG[p*12 + r*4 + 0] * sR[i*9 + 0 + cc]
                  + sG[p*12 + r*4 + 1] * sR[i*9 + 3 + cc]
                  + sG[p*12 + r*4 + 2] * sR[i*9 + 6 + cc];
            } else {
                float tx = sJ[i*3+0] - sJ[p*3+0];
                float ty = sJ[i*3+1] - sJ[p*3+1];
                float tz = sJ[i*3+2] - sJ[p*3+2];
                v = sG[p*12 + r*4 + 0] * tx
                  + sG[p*12 + r*4 + 1] * ty
                  + sG[p*12 + r*4 + 2] * tz
                  + sG[p*12 + r*4 + 3];
            }
            sG[i*12 + r*4 + cc] = v;
            __syncwarp(0x0fff);
        }
    }
    __syncthreads();

    if (tid < 72) {
        int k = tid / 3, c = tid - k*3;
        sAt[k*3 + c] = sG[k*12 + c*4 + 3]
                     - (sG[k*12 + c*4 + 0] * sJ[k*3 + 0]
                      + sG[k*12 + c*4 + 1] * sJ[k*3 + 1]
                      + sG[k*12 + c*4 + 2] * sJ[k*3 + 2]);
    }
    __syncthreads();

    if (tid < 72) {
        int j = tid / 3, c = tid - j*3;
        const float* qb = Qv + (size_t)b * NQ;
        const float* s0 = C2 + 218 * N2;
        float acc = 0.f;
#pragma unroll
        for (int k = 0; k < 24; k++) {
            int jk = j*24 + k;
            acc = fmaf(sG[k*12 + c*4 + 0], qb[jk],        acc);
            acc = fmaf(sG[k*12 + c*4 + 1], qb[576 + jk],  acc);
            acc = fmaf(sG[k*12 + c*4 + 2], qb[1152 + jk], acc);
            acc = fmaf(sAt[k*3 + c],       s0[jk],        acc);
        }
        out[b*72 + j*3 + c] = acc;
    }
}

// ---------------- launcher ----------------
extern "C" void kernel_launch(void* const* d_in, const int* in_sizes, int n_in,
                              void* d_out, int out_size)
{
    const float* beta      = (const float*)d_in[0];
    const float* theta     = (const float*)d_in[1];
    const float* vtempl    = (const float*)d_in[2];
    const float* shapedirs = (const float*)d_in[3];
    const float* posedirs  = (const float*)d_in[4];
    const float* Jr        = (const float*)d_in[5];
    const float* wts       = (const float*)d_in[6];
    float* out = (float*)d_out;

    __nv_bfloat16 *Ah, *Al, *Bh, *Bl, *Bth, *Btl, *gh, *gl;
    float *Jrt, *wt, *Cpart, *C2, *Jb, *Rs, *Qv;
    cudaGetSymbolAddress((void**)&Ah, d_Ah);
    cudaGetSymbolAddress((void**)&Al, d_Al);
    cudaGetSymbolAddress((void**)&Bh, d_Bh);
    cudaGetSymbolAddress((void**)&Bl, d_Bl);
    cudaGetSymbolAddress((void**)&Bth, d_Bth);
    cudaGetSymbolAddress((void**)&Btl, d_Btl);
    cudaGetSymbolAddress((void**)&gh, d_gh);
    cudaGetSymbolAddress((void**)&gl, d_gl);
    cudaGetSymbolAddress((void**)&Jrt, d_Jrt);
    cudaGetSymbolAddress((void**)&wt, d_wt);
    cudaGetSymbolAddress((void**)&Cpart, d_Cpart);
    cudaGetSymbolAddress((void**)&C2, d_C2);
    cudaGetSymbolAddress((void**)&Jb, d_Jb);
    cudaGetSymbolAddress((void**)&Rs, d_Rs);
    cudaGetSymbolAddress((void**)&Qv, d_Qv);

    cudaFuncSetAttribute(k_mma,    cudaFuncAttributeMaxDynamicSharedMemorySize, GSMEM);
    cudaFuncSetAttribute(k_gemm3m, cudaFuncAttributeMaxDynamicSharedMemorySize, GSMEM);

    k_prep<<<dim3(KPAD/256, TROWS + NJ), 256>>>(posedirs, shapedirs, vtempl, Jr, wts,
                                                Ah, Al, Jrt, wt);
    k_prepB<<<dim3(KPAD/256, N2), 256>>>(Jrt, wt, Bh, Bl);
    k_mma<<<dim3(N2/BN, MPAD/BM, ZSPL), 256, GSMEM>>>(Ah, Al, Bh, Bl, Cpart);
    k_reduce<<<dim3(N2/32, M2/32), dim3(32, 8)>>>(Cpart, C2, Bth, Btl);
    k_featjb<<<NB + 1, 128>>>(beta, theta, C2, gh, gl, Rs, Jb);
    k_gemm3m<<<dim3(NQ/BN, NB/BM), 256, GSMEM>>>(gh, gl, Bth, Btl, Qv);
    k_final<<<NB, 128>>>(beta, Rs, Jb, C2, Qv, out);
}

// round 6
// speedup vs baseline: 2.9836x; 1.1520x over previous
#include <cuda_runtime.h>
#include <cuda_bf16.h>
#include <math.h>
#include <stdint.h>

// ---------------- problem constants ----------------
#define NB     1024
#define NV     6890
#define NJ     24
#define NPOSE  207
#define TROWS  224
#define M2     672      // 3 * TROWS
#define MPAD   768
#define N2     576      // jk pairs
#define NQ     1728     // 3 * 576
#define KPAD   6912
#define GDIM   224

// big GEMM tiling (segment-folded)
#define BM 128
#define BN 64
#define BK 32
#define AHSZ (BM*BK*2)        // 8192 B per A half
#define BHSZ (BN*BK*2)        // 4096 B per B half
#define MSTG (2*AHSZ + 2*BHSZ) // 24576 B per stage
#define MNST 3
#define MSMEM (MNST*MSTG)     // 73728 B
#define ZSPL 8                // K-subsplits (432 CTAs = single wave @3/SM)
#define KIT  27               // 864/32 k-blocks per CTA

// small GEMM tiling (unchanged scheme)
#define SASZ 8192
#define SBSZ 4096
#define SSTG 12288
#define SSMEM (4*SSTG)        // 49152
#define G3ITER 21             // 3 segments x 224/32

__constant__ int c_parents[24] = {-1,0,0,0,1,2,3,4,5,6,7,8,9,9,9,12,13,14,16,17,18,19,20,21};

// ---------------- device scratch ----------------
__device__ __align__(16) __nv_bfloat16 d_Ah[MPAD * KPAD];
__device__ __align__(16) __nv_bfloat16 d_Al[MPAD * KPAD];
__device__ __align__(16) __nv_bfloat16 d_Bh[N2 * KPAD];
__device__ __align__(16) __nv_bfloat16 d_Bl[N2 * KPAD];
__device__ float d_Jrt[NJ * KPAD];
__device__ float d_wt [NJ * KPAD];
__device__ float d_C2[MPAD * N2];                         // red.add target (zeroed per launch)
__device__ __align__(16) __nv_bfloat16 d_Bth[NQ * GDIM];  // C2 transposed hi
__device__ __align__(16) __nv_bfloat16 d_Btl[NQ * GDIM];  // C2 transposed lo
__device__ float d_Jb[3 * 11 * NJ];
__device__ __align__(16) __nv_bfloat16 d_gh[NB * GDIM];
__device__ __align__(16) __nv_bfloat16 d_gl[NB * GDIM];
__device__ float d_Rs[NB * NJ * 9];
__device__ float d_Qv[NB * NQ];

// ---------------- helpers ----------------
__device__ __forceinline__ uint32_t smem_u32(const void* p) {
    uint32_t r;
    asm("{ .reg .u64 t; cvta.to.shared.u64 t, %1; cvt.u32.u64 %0, t; }" : "=r"(r) : "l"(p));
    return r;
}
__device__ __forceinline__ void cp_async16(uint32_t saddr, const void* gaddr) {
    asm volatile("cp.async.cg.shared.global [%0], [%1], 16;" :: "r"(saddr), "l"(gaddr) : "memory");
}
__device__ __forceinline__ void cp_commit() {
    asm volatile("cp.async.commit_group;" ::: "memory");
}
__device__ __forceinline__ void ldsm_x4(uint32_t& r0, uint32_t& r1, uint32_t& r2, uint32_t& r3,
                                        uint32_t addr) {
    asm volatile("ldmatrix.sync.aligned.m8n8.x4.shared.b16 {%0,%1,%2,%3}, [%4];"
                 : "=r"(r0), "=r"(r1), "=r"(r2), "=r"(r3) : "r"(addr));
}
__device__ __forceinline__ void mma16816(float& d0, float& d1, float& d2, float& d3,
                                         uint32_t a0, uint32_t a1, uint32_t a2, uint32_t a3,
                                         uint32_t b0, uint32_t b1) {
    asm volatile("mma.sync.aligned.m16n8k16.row.col.f32.bf16.bf16.f32 "
                 "{%0,%1,%2,%3}, {%4,%5,%6,%7}, {%8,%9}, {%0,%1,%2,%3};"
                 : "+f"(d0), "+f"(d1), "+f"(d2), "+f"(d3)
                 : "r"(a0), "r"(a1), "r"(a2), "r"(a3), "r"(b0), "r"(b1));
}
// swizzled byte offset in a [rows][32 bf16] tile: row r, 16B chunk c in 0..3
__device__ __forceinline__ uint32_t swz32(int r, int c) {
    return (uint32_t)(r * 64 + ((c ^ ((r >> 1) & 3)) << 4));
}

// ---------------- prep: gather basis rows (A) + transpose Jr/w ----------------
__global__ void k_prep(const float* __restrict__ posedirs,
                       const float* __restrict__ shapedirs,
                       const float* __restrict__ vtempl,
                       const float* __restrict__ Jr, const float* __restrict__ w,
                       __nv_bfloat16* __restrict__ Ah, __nv_bfloat16* __restrict__ Al,
                       float* __restrict__ Jrt, float* __restrict__ wt)
{
    int v = blockIdx.x * 256 + threadIdx.x;
    int y = blockIdx.y;
    if (y < TROWS) {
        int t = y;
        float val[3] = {0.f, 0.f, 0.f};
        if (v < NV) {
            if (t < NPOSE) {
                val[0] = posedirs[(size_t)t * (NV*3) + v*3 + 0];
                val[1] = posedirs[(size_t)t * (NV*3) + v*3 + 1];
                val[2] = posedirs[(size_t)t * (NV*3) + v*3 + 2];
            } else if (t < NPOSE + 10) {
                val[0] = shapedirs[(size_t)(t-NPOSE) * (NV*3) + v*3 + 0];
                val[1] = shapedirs[(size_t)(t-NPOSE) * (NV*3) + v*3 + 1];
                val[2] = shapedirs[(size_t)(t-NPOSE) * (NV*3) + v*3 + 2];
            } else if (t == 217) {
                val[0] = vtempl[v*3 + 0];
                val[1] = vtempl[v*3 + 1];
                val[2] = vtempl[v*3 + 2];
            } else if (t == 218) {
                val[0] = 1.f;
            }
        }
#pragma unroll
        for (int c = 0; c < 3; ++c) {
            __nv_bfloat16 h = __float2bfloat16(val[c]);
            __nv_bfloat16 l = __float2bfloat16(val[c] - __bfloat162float(h));
            size_t idx = (size_t)(c*TROWS + t) * KPAD + v;
            Ah[idx] = h;
            Al[idx] = l;
        }
    } else {
        int j = y - TROWS;
        float a = 0.f, b = 0.f;
        if (v < NV) { a = Jr[v*24 + j]; b = w[v*24 + j]; }
        Jrt[(size_t)j * KPAD + v] = a;
        wt [(size_t)j * KPAD + v] = b;
    }
}

// ---------------- B[jk][v] = Jr[v,j]*w[v,k] -> bf16 hi/lo ----------------
__global__ void k_prepB(const float* __restrict__ Jrt, const float* __restrict__ wt,
                        __nv_bfloat16* __restrict__ Bh, __nv_bfloat16* __restrict__ Bl)
{
    int v = blockIdx.x * 256 + threadIdx.x;
    int jk = blockIdx.y;
    int j = jk / 24, k = jk - j * 24;
    float val = Jrt[(size_t)j * KPAD + v] * wt[(size_t)k * KPAD + v];
    __nv_bfloat16 h = __float2bfloat16(val);
    __nv_bfloat16 l = __float2bfloat16(val - __bfloat162float(h));
    size_t idx = (size_t)jk * KPAD + v;
    Bh[idx] = h;
    Bl[idx] = l;
}

// ---------------- big projection GEMM, segment-folded, red.add epilogue --------
__global__ __launch_bounds__(256, 3) void k_mma(const __nv_bfloat16* __restrict__ Ah,
                                                const __nv_bfloat16* __restrict__ Al,
                                                const __nv_bfloat16* __restrict__ Bh,
                                                const __nv_bfloat16* __restrict__ Bl,
                                                float* __restrict__ C2)
{
    extern __shared__ char sm[];
    const uint32_t sbase = smem_u32(sm);
    const int tid = threadIdx.x;
    const int lane = tid & 31, wid = tid >> 5;
    const int n0 = blockIdx.x * BN;
    const int m0 = blockIdx.y * BM;
    const int kbase = blockIdx.z * (KIT * BK);

    const int wm = wid & 3;
    const int wn = wid >> 2;

    const int lr = tid >> 2, lc = tid & 3;   // loader: row 0..63, chunk 0..3

    auto load_stage = [&](int t) {
        const uint32_t s0 = sbase + (uint32_t)(t % MNST) * MSTG;
        const uint32_t sAh = s0;
        const uint32_t sAl = s0 + AHSZ;
        const uint32_t sBh = s0 + 2*AHSZ;
        const uint32_t sBl = s0 + 2*AHSZ + BHSZ;
        const int kk = kbase + t * BK;
        cp_async16(sAh + swz32(lr,      lc), Ah + (size_t)(m0 + lr)      * KPAD + kk + lc*8);
        cp_async16(sAh + swz32(lr + 64, lc), Ah + (size_t)(m0 + lr + 64) * KPAD + kk + lc*8);
        cp_async16(sAl + swz32(lr,      lc), Al + (size_t)(m0 + lr)      * KPAD + kk + lc*8);
        cp_async16(sAl + swz32(lr + 64, lc), Al + (size_t)(m0 + lr + 64) * KPAD + kk + lc*8);
        cp_async16(sBh + swz32(lr, lc), Bh + (size_t)(n0 + lr) * KPAD + kk + lc*8);
        cp_async16(sBl + swz32(lr, lc), Bl + (size_t)(n0 + lr) * KPAD + kk + lc*8);
        cp_commit();
    };

    float acc[2][4][4] = {};

    load_stage(0);
    load_stage(1);

    for (int t = 0; t < KIT; ++t) {
        asm volatile("cp.async.wait_group 1;" ::: "memory");
        __syncthreads();
        if (t + 2 < KIT) load_stage(t + 2);

        const uint32_t s0 = sbase + (uint32_t)(t % MNST) * MSTG;
        const uint32_t sAh = s0;
        const uint32_t sAl = s0 + AHSZ;
        const uint32_t sBh = s0 + 2*AHSZ;
        const uint32_t sBl = s0 + 2*AHSZ + BHSZ;

#pragma unroll
        for (int ks = 0; ks < 2; ++ks) {
            // A-hi fragments
            uint32_t ah[2][4];
#pragma unroll
            for (int i = 0; i < 2; i++) {
                int r = wm*32 + i*16 + (lane & 15);
                int c = ks*2 + (lane >> 4);
                ldsm_x4(ah[i][0], ah[i][1], ah[i][2], ah[i][3], sAh + swz32(r, c));
            }
            // B-hi fragments
            uint32_t bh[4][2];
#pragma unroll
            for (int j2 = 0; j2 < 2; j2++) {
                int n = wn*32 + j2*16 + (lane & 7) + ((lane >> 4) << 3);
                int c = ks*2 + ((lane >> 3) & 1);
                uint32_t q0, q1, q2, q3;
                ldsm_x4(q0, q1, q2, q3, sBh + swz32(n, c));
                bh[j2*2+0][0] = q0; bh[j2*2+0][1] = q1;
                bh[j2*2+1][0] = q2; bh[j2*2+1][1] = q3;
            }
            // pass 1: Ah x Bh
#pragma unroll
            for (int i = 0; i < 2; i++)
#pragma unroll
                for (int j = 0; j < 4; j++)
                    mma16816(acc[i][j][0], acc[i][j][1], acc[i][j][2], acc[i][j][3],
                             ah[i][0], ah[i][1], ah[i][2], ah[i][3], bh[j][0], bh[j][1]);
            // B-lo fragments, pass 2: Ah x Bl (reuse ah)
            uint32_t bl[4][2];
#pragma unroll
            for (int j2 = 0; j2 < 2; j2++) {
                int n = wn*32 + j2*16 + (lane & 7) + ((lane >> 4) << 3);
                int c = ks*2 + ((lane >> 3) & 1);
                uint32_t q0, q1, q2, q3;
                ldsm_x4(q0, q1, q2, q3, sBl + swz32(n, c));
                bl[j2*2+0][0] = q0; bl[j2*2+0][1] = q1;
                bl[j2*2+1][0] = q2; bl[j2*2+1][1] = q3;
            }
#pragma unroll
            for (int i = 0; i < 2; i++)
#pragma unroll
                for (int j = 0; j < 4; j++)
                    mma16816(acc[i][j][0], acc[i][j][1], acc[i][j][2], acc[i][j][3],
                             ah[i][0], ah[i][1], ah[i][2], ah[i][3], bl[j][0], bl[j][1]);
            // A-lo fragments, pass 3: Al x Bh (reuse bh)
            uint32_t al[2][4];
#pragma unroll
            for (int i = 0; i < 2; i++) {
                int r = wm*32 + i*16 + (lane & 15);
                int c = ks*2 + (lane >> 4);
                ldsm_x4(al[i][0], al[i][1], al[i][2], al[i][3], sAl + swz32(r, c));
            }
#pragma unroll
            for (int i = 0; i < 2; i++)
#pragma unroll
                for (int j = 0; j < 4; j++)
                    mma16816(acc[i][j][0], acc[i][j][1], acc[i][j][2], acc[i][j][3],
                             al[i][0], al[i][1], al[i][2], al[i][3], bh[j][0], bh[j][1]);
        }
    }

    // red.add epilogue into zero-initialized C2
#pragma unroll
    for (int i = 0; i < 2; i++) {
        int row = m0 + wm*32 + i*16 + (lane >> 2);
#pragma unroll
        for (int j = 0; j < 4; j++) {
            int col = n0 + wn*32 + j*8 + (lane & 3)*2;
            atomicAdd(C2 + (size_t)row * N2 + col,           acc[i][j][0]);
            atomicAdd(C2 + (size_t)row * N2 + col + 1,       acc[i][j][1]);
            atomicAdd(C2 + (size_t)(row + 8) * N2 + col,     acc[i][j][2]);
            atomicAdd(C2 + (size_t)(row + 8) * N2 + col + 1, acc[i][j][3]);
        }
    }
}

// ---------------- transpose C2 -> bf16 hi/lo [c*N2+n][t] ----------------
__global__ void k_tr2(const float* __restrict__ C2,
                      __nv_bfloat16* __restrict__ Bth, __nv_bfloat16* __restrict__ Btl)
{
    __shared__ float s[32][33];
    const int n0 = blockIdx.x * 32;
    const int m0 = blockIdx.y * 32;
    const int tx = threadIdx.x, ty = threadIdx.y;

#pragma unroll
    for (int q = 0; q < 4; ++q)
        s[ty + q*8][tx] = C2[(size_t)(m0 + ty + q*8) * N2 + n0 + tx];
    __syncthreads();

    const int c  = m0 / TROWS;   // 224 = 7*32, tiles never straddle channels
    const int t0 = m0 - c * TROWS;
#pragma unroll
    for (int q = 0; q < 4; ++q) {
        int n = n0 + ty + q*8;
        float v = s[tx][ty + q*8];
        __nv_bfloat16 h = __float2bfloat16(v);
        __nv_bfloat16 l = __float2bfloat16(v - __bfloat162float(h));
        size_t o = (size_t)(c*N2 + n) * GDIM + t0 + tx;
        Bth[o] = h;
        Btl[o] = l;
    }
}

// ---------------- Rodrigues + features (bf16 hi/lo) + rest-joint basis ---------
__global__ void k_featjb(const float* __restrict__ beta,
                         const float* __restrict__ theta,
                         const float* __restrict__ C2,
                         __nv_bfloat16* __restrict__ gh, __nv_bfloat16* __restrict__ gl,
                         float* __restrict__ Rs, float* __restrict__ Jb)
{
    int b = blockIdx.x;
    int lane = threadIdx.x;
    if (b == NB) {
        for (int idx = lane; idx < 3*11*NJ; idx += 128) {
            int c = idx / (11*NJ);
            int r = idx - c * (11*NJ);
            int i = r / NJ;
            int j = r - i * NJ;
            const float* row = C2 + (size_t)(c*TROWS + 207 + i) * N2 + j*24;
            float s = 0.f;
#pragma unroll
            for (int k = 0; k < 24; k++) s += row[k];
            Jb[idx] = s;
        }
        return;
    }
    auto wr = [&](int idx, float v) {
        __nv_bfloat16 h = __float2bfloat16(v);
        __nv_bfloat16 l = __float2bfloat16(v - __bfloat162float(h));
        gh[(size_t)b*GDIM + idx] = h;
        gl[(size_t)b*GDIM + idx] = l;
    };
    if (lane < 24) {
        int k = lane;
        float t0 = theta[b*72 + k*3 + 0];
        float t1 = theta[b*72 + k*3 + 1];
        float t2 = theta[b*72 + k*3 + 2];
        float a0 = t0 + 1e-8f, a1 = t1 + 1e-8f, a2 = t2 + 1e-8f;
        float angle = sqrtf(a0*a0 + a1*a1 + a2*a2);
        float inv = 1.f / angle;
        float n0 = t0*inv, n1 = t1*inv, n2 = t2*inv;
        float half = 0.5f * angle;
        float w = cosf(half), s = sinf(half);
        float x = s*n0, y = s*n1, z = s*n2;
        float qn = rsqrtf(w*w + x*x + y*y + z*z);
        w *= qn; x *= qn; y *= qn; z *= qn;
        float rot[9];
        rot[0] = w*w + x*x - y*y - z*z;
        rot[1] = 2.f*(x*y - w*z);
        rot[2] = 2.f*(x*z + w*y);
        rot[3] = 2.f*(x*y + w*z);
        rot[4] = w*w - x*x + y*y - z*z;
        rot[5] = 2.f*(y*z - w*x);
        rot[6] = 2.f*(x*z - w*y);
        rot[7] = 2.f*(y*z + w*x);
        rot[8] = w*w - x*x - y*y + z*z;
        float* rs = Rs + (size_t)(b*24 + k) * 9;
#pragma unroll
        for (int e = 0; e < 9; e++) rs[e] = rot[e];
        if (k > 0) {
#pragma unroll
            for (int e = 0; e < 9; e++)
                wr((k-1)*9 + e, rot[e] - ((e == 0 || e == 4 || e == 8) ? 1.f : 0.f));
        }
    }
    if (lane < 10)       wr(207 + lane, beta[b*10 + lane]);
    else if (lane == 10) wr(217, 1.f);
    else if (lane < 17)  wr(207 + lane, 0.f);
}

// ---------------- per-batch GEMM Qv = g @ C2t^T (bf16 mma, 3 passes) ------------
__global__ __launch_bounds__(256) void k_gemm3m(const __nv_bfloat16* __restrict__ gh,
                                                const __nv_bfloat16* __restrict__ gl,
                                                const __nv_bfloat16* __restrict__ Bth,
                                                const __nv_bfloat16* __restrict__ Btl,
                                                float* __restrict__ Qv)
{
    extern __shared__ char sm[];
    const uint32_t sbase = smem_u32(sm);
    const int tid = threadIdx.x;
    const int lane = tid & 31, wid = tid >> 5;
    const int n0 = blockIdx.x * BN;
    const int m0 = blockIdx.y * BM;

    const int wm = wid & 3;
    const int wn = wid >> 2;
    const int lrA0 = tid >> 2, lcA0 = tid & 3;
    const int lrA1 = (tid + 256) >> 2;

    auto load_stage = [&](int t) {
        const int seg = t / 7;
        const int kk = (t - seg*7) * BK;
        const __nv_bfloat16* Aptr = (seg == 2) ? gl : gh;
        const __nv_bfloat16* Bptr = (seg == 1) ? Btl : Bth;
        const uint32_t sa = sbase + (uint32_t)(t & 3) * SSTG;
        const uint32_t sb = sa + SASZ;
        cp_async16(sa + swz32(lrA0, lcA0), Aptr + (size_t)(m0 + lrA0) * GDIM + kk + lcA0*8);
        cp_async16(sa + swz32(lrA1, lcA0), Aptr + (size_t)(m0 + lrA1) * GDIM + kk + lcA0*8);
        cp_async16(sb + swz32(lrA0, lcA0), Bptr + (size_t)(n0 + lrA0) * GDIM + kk + lcA0*8);
        cp_commit();
    };

    float acc[2][4][4] = {};

    load_stage(0);
    load_stage(1);
    load_stage(2);

    for (int t = 0; t < G3ITER; ++t) {
        asm volatile("cp.async.wait_group 2;" ::: "memory");
        __syncthreads();
        if (t + 3 < G3ITER) load_stage(t + 3);

        const uint32_t sa = sbase + (uint32_t)(t & 3) * SSTG;
        const uint32_t sb = sa + SASZ;
#pragma unroll
        for (int ks = 0; ks < 2; ++ks) {
            uint32_t a[2][4];
#pragma unroll
            for (int i = 0; i < 2; i++) {
                int r = wm*32 + i*16 + (lane & 15);
                int c = ks*2 + (lane >> 4);
                ldsm_x4(a[i][0], a[i][1], a[i][2], a[i][3], sa + swz32(r, c));
            }
            uint32_t bfr[4][2];
#pragma unroll
            for (int j2 = 0; j2 < 2; j2++) {
                int n = wn*32 + j2*16 + (lane & 7) + ((lane >> 4) << 3);
                int c = ks*2 + ((lane >> 3) & 1);
                uint32_t q0, q1, q2, q3;
                ldsm_x4(q0, q1, q2, q3, sb + swz32(n, c));
                bfr[j2*2+0][0] = q0; bfr[j2*2+0][1] = q1;
                bfr[j2*2+1][0] = q2; bfr[j2*2+1][1] = q3;
            }
#pragma unroll
            for (int i = 0; i < 2; i++)
#pragma unroll
                for (int j = 0; j < 4; j++)
                    mma16816(acc[i][j][0], acc[i][j][1], acc[i][j][2], acc[i][j][3],
                             a[i][0], a[i][1], a[i][2], a[i][3],
                             bfr[j][0], bfr[j][1]);
        }
    }

#pragma unroll
    for (int i = 0; i < 2; i++) {
        int row = m0 + wm*32 + i*16 + (lane >> 2);
#pragma unroll
        for (int j = 0; j < 4; j++) {
            int col = n0 + wn*32 + j*8 + (lane & 3)*2;
            *(float2*)(Qv + (size_t)row * NQ + col)       = make_float2(acc[i][j][0], acc[i][j][1]);
            *(float2*)(Qv + (size_t)(row + 8) * NQ + col) = make_float2(acc[i][j][2], acc[i][j][3]);
        }
    }
}

// ---------------- kinematic chain + combine ----------------
__global__ __launch_bounds__(128) void k_final(const float* __restrict__ beta,
                                               const float* __restrict__ Rs,
                                               const float* __restrict__ Jb,
                                               const float* __restrict__ C2,
                                               const float* __restrict__ Qv,
                                               float* __restrict__ out)
{
    __shared__ float sR[216];
    __shared__ float sJ[72];
    __shared__ float sG[288];
    __shared__ float sAt[72];
    __shared__ float sBeta[10];
    const int b = blockIdx.x;
    const int tid = threadIdx.x;

    for (int i = tid; i < 216; i += 128) sR[i] = Rs[(size_t)b*216 + i];
    if (tid < 10) sBeta[tid] = beta[b*10 + tid];
    __syncthreads();

    if (tid < 72) {
        int j = tid / 3, c = tid - j*3;
        float v = Jb[(c*11 + 10)*NJ + j];
#pragma unroll
        for (int i = 0; i < 10; i++) v = fmaf(sBeta[i], Jb[(c*11 + i)*NJ + j], v);
        sJ[j*3 + c] = v;
    }
    __syncthreads();

    if (tid < 12) {
        int r = tid >> 2, cc = tid & 3;
        sG[tid] = (cc < 3) ? sR[r*3 + cc] : sJ[r];
        __syncwarp(0x0fff);
        for (int i = 1; i < 24; i++) {
            int p = c_parents[i];
            float v;
            if (cc < 3) {
                v = sG[p*12 + r*4 + 0] * sR[i*9 + 0 + cc]
                  + sG[p*12 + r*4 + 1] * sR[i*9 + 3 + cc]
                  + sG[p*12 + r*4 + 2] * sR[i*9 + 6 + cc];
            } else {
                float tx = sJ[i*3+0] - sJ[p*3+0];
                float ty = sJ[i*3+1] - sJ[p*3+1];
                float tz = sJ[i*3+2] - sJ[p*3+2];
                v = sG[p*12 + r*4 + 0] * tx
                  + sG[p*12 + r*4 + 1] * ty
                  + sG[p*12 + r*4 + 2] * tz
                  + sG[p*12 + r*4 + 3];
            }
            sG[i*12 + r*4 + cc] = v;
            __syncwarp(0x0fff);
        }
    }
    __syncthreads();

    if (tid < 72) {
        int k = tid / 3, c = tid - k*3;
        sAt[k*3 + c] = sG[k*12 + c*4 + 3]
                     - (sG[k*12 + c*4 + 0] * sJ[k*3 + 0]
                      + sG[k*12 + c*4 + 1] * sJ[k*3 + 1]
                      + sG[k*12 + c*4 + 2] * sJ[k*3 + 2]);
    }
    __syncthreads();

    if (tid < 72) {
        int j = tid / 3, c = tid - j*3;
        const float* qb = Qv + (size_t)b * NQ;
        const float* s0 = C2 + 218 * N2;
        float acc = 0.f;
#pragma unroll
        for (int k = 0; k < 24; k++) {
            int jk = j*24 + k;
            acc = fmaf(sG[k*12 + c*4 + 0], qb[jk],        acc);
            acc = fmaf(sG[k*12 + c*4 + 1], qb[576 + jk],  acc);
            acc = fmaf(sG[k*12 + c*4 + 2], qb[1152 + jk], acc);
            acc = fmaf(sAt[k*3 + c],       s0[jk],        acc);
        }
        out[b*72 + j*3 + c] = acc;
    }
}

// ---------------- launcher ----------------
extern "C" void kernel_launch(void* const* d_in, const int* in_sizes, int n_in,
                              void* d_out, int out_size)
{
    const float* beta      = (const float*)d_in[0];
    const float* theta     = (const float*)d_in[1];
    const float* vtempl    = (const float*)d_in[2];
    const float* shapedirs = (const float*)d_in[3];
    const float* posedirs  = (const float*)d_in[4];
    const float* Jr        = (const float*)d_in[5];
    const float* wts       = (const float*)d_in[6];
    float* out = (float*)d_out;

    __nv_bfloat16 *Ah, *Al, *Bh, *Bl, *Bth, *Btl, *gh, *gl;
    float *Jrt, *wt, *C2, *Jb, *Rs, *Qv;
    cudaGetSymbolAddress((void**)&Ah, d_Ah);
    cudaGetSymbolAddress((void**)&Al, d_Al);
    cudaGetSymbolAddress((void**)&Bh, d_Bh);
    cudaGetSymbolAddress((void**)&Bl, d_Bl);
    cudaGetSymbolAddress((void**)&Bth, d_Bth);
    cudaGetSymbolAddress((void**)&Btl, d_Btl);
    cudaGetSymbolAddress((void**)&gh, d_gh);
    cudaGetSymbolAddress((void**)&gl, d_gl);
    cudaGetSymbolAddress((void**)&Jrt, d_Jrt);
    cudaGetSymbolAddress((void**)&wt, d_wt);
    cudaGetSymbolAddress((void**)&C2, d_C2);
    cudaGetSymbolAddress((void**)&Jb, d_Jb);
    cudaGetSymbolAddress((void**)&Rs, d_Rs);
    cudaGetSymbolAddress((void**)&Qv, d_Qv);

    cudaFuncSetAttribute(k_mma,    cudaFuncAttributeMaxDynamicSharedMemorySize, MSMEM);
    cudaFuncSetAttribute(k_gemm3m, cudaFuncAttributeMaxDynamicSharedMemorySize, SSMEM);

    cudaMemsetAsync(C2, 0, (size_t)MPAD * N2 * sizeof(float), 0);
    k_prep<<<dim3(KPAD/256, TROWS + NJ), 256>>>(posedirs, shapedirs, vtempl, Jr, wts,
                                                Ah, Al, Jrt, wt);
    k_prepB<<<dim3(KPAD/256, N2), 256>>>(Jrt, wt, Bh, Bl);
    k_mma<<<dim3(N2/BN, MPAD/BM, ZSPL), 256, MSMEM>>>(Ah, Al, Bh, Bl, C2);
    k_tr2<<<dim3(N2/32, M2/32), dim3(32, 8)>>>(C2, Bth, Btl);
    k_featjb<<<NB + 1, 128>>>(beta, theta, C2, gh, gl, Rs, Jb);
    k_gemm3m<<<dim3(NQ/BN, NB/BM), 256, SSMEM>>>(gh, gl, Bth, Btl, Qv);
    k_final<<<NB, 128>>>(beta, Rs, Jb, C2, Qv, out);
}